// round 3
// baseline (speedup 1.0000x reference)
#include <cuda_runtime.h>
#include <cuda_bf16.h>
#include <cstdint>

// Problem constants
#define BB 8
#define LL 2048
#define DD 512
#define II 256
#define SS 8
#define DTR 32
#define ROWS (BB*LL)          // 16384
#define UCOLS 1536

// ---------------- scratch (static device globals; no runtime alloc) -------
__device__ float g_h    [ROWS * 128];        // pos hidden
__device__ float g_pos  [ROWS * DD];         // pos MLP output
__device__ float g_ubig [ROWS * UCOLS];      // [y_f, zb_f, y_b, zb_b, si]
__device__ float g_xz   [ROWS * DD];         // in-proj output (reused per dir)
__device__ float g_delta[2 * ROWS * II];
__device__ float g_xbuf [2 * ROWS * II];
__device__ float g_bt   [2 * ROWS * SS];
__device__ float g_ct   [2 * ROWS * SS];
__device__ float g_mixed[ROWS * DD];
__device__ float g_owT  [2 * DD * DD];       // transposed scan_out_w
__device__ float g_wbig [DD * UCOLS];        // folded mix weight [512,1536]

// ---------------- generic SGEMM: C[m,n] = sum_k A[m,k] * W[n,k] -----------
// BM=128, BN=64, BK=16, 256 threads, 8x4 per thread.
// Requires: M%128==0, N%64==0, K%16==0, lda/ldw/ldc multiples of 4.
__global__ __launch_bounds__(256) void sgemm_tn(
    const float* __restrict__ A, int lda,
    const float* __restrict__ W, int ldw,
    float* __restrict__ C, int ldc, int K)
{
    __shared__ float As[16][128];
    __shared__ float Ws[16][64];
    const int bm = blockIdx.y * 128;
    const int bn = blockIdx.x * 64;
    const int tid = threadIdx.x;
    const int tx = tid & 15;   // n group
    const int ty = tid >> 4;   // m group
    float acc[8][4];
    #pragma unroll
    for (int m = 0; m < 8; m++)
        #pragma unroll
        for (int n = 0; n < 4; n++) acc[m][n] = 0.f;

    for (int k0 = 0; k0 < K; k0 += 16) {
        #pragma unroll
        for (int u = 0; u < 2; u++) {
            int f = tid + u * 256;            // 0..511
            int row = f >> 2;
            int kk = (f & 3) * 4;
            float4 v = *reinterpret_cast<const float4*>(
                &A[(size_t)(bm + row) * lda + k0 + kk]);
            As[kk + 0][row] = v.x; As[kk + 1][row] = v.y;
            As[kk + 2][row] = v.z; As[kk + 3][row] = v.w;
        }
        {
            int row = tid >> 2;
            int kk = (tid & 3) * 4;
            float4 v = *reinterpret_cast<const float4*>(
                &W[(size_t)(bn + row) * ldw + k0 + kk]);
            Ws[kk + 0][row] = v.x; Ws[kk + 1][row] = v.y;
            Ws[kk + 2][row] = v.z; Ws[kk + 3][row] = v.w;
        }
        __syncthreads();
        #pragma unroll
        for (int kk = 0; kk < 16; kk++) {
            float af[8], wf[4];
            #pragma unroll
            for (int m = 0; m < 8; m++) af[m] = As[kk][ty * 8 + m];
            #pragma unroll
            for (int n = 0; n < 4; n++) wf[n] = Ws[kk][tx * 4 + n];
            #pragma unroll
            for (int m = 0; m < 8; m++)
                #pragma unroll
                for (int n = 0; n < 4; n++)
                    acc[m][n] = fmaf(af[m], wf[n], acc[m][n]);
        }
        __syncthreads();
    }
    #pragma unroll
    for (int m = 0; m < 8; m++) {
        float4 v = make_float4(acc[m][0], acc[m][1], acc[m][2], acc[m][3]);
        *reinterpret_cast<float4*>(
            &C[(size_t)(bm + ty * 8 + m) * ldc + bn + tx * 4]) = v;
    }
}

// ---------------- transpose 512x512 (per dir) ------------------------------
__global__ void k_transpose(const float* __restrict__ src, float* __restrict__ dst)
{
    __shared__ float tile[32][33];
    int d = blockIdx.z;
    src += (size_t)d * DD * DD;
    dst += (size_t)d * DD * DD;
    int x = blockIdx.x * 32 + threadIdx.x;
    int y = blockIdx.y * 32 + threadIdx.y;
    tile[threadIdx.y][threadIdx.x] = src[(size_t)y * DD + x];
    __syncthreads();
    x = blockIdx.y * 32 + threadIdx.x;
    y = blockIdx.x * 32 + threadIdx.y;
    dst[(size_t)y * DD + x] = tile[threadIdx.x][threadIdx.y];
}

// copy mix_w[:,1024:1536] into g_wbig[:,1024:1536]
__global__ void k_copytail(const float* __restrict__ mixw, float* __restrict__ wbig)
{
    int idx = blockIdx.x * 256 + threadIdx.x;   // 0..262143
    int n = idx >> 9, j = idx & 511;
    wbig[(size_t)n * UCOLS + 1024 + j] = mixw[(size_t)n * UCOLS + 1024 + j];
}

// ---------------- position MLP layer 1 (6 -> 128, exact GELU) --------------
__global__ void k_pos_h(const float* __restrict__ position,
                        const float* __restrict__ pw1,
                        const float* __restrict__ pb1,
                        float* __restrict__ h)
{
    int r = blockIdx.x, j = threadIdx.x;      // 128 threads
    __shared__ float p[6];
    if (j < 6) p[j] = position[(size_t)r * 6 + j];
    __syncthreads();
    float acc = pb1[j];
    #pragma unroll
    for (int c = 0; c < 6; c++) acc = fmaf(pw1[j * 6 + c], p[c], acc);
    float g = 0.5f * acc * (1.f + erff(acc * 0.70710678118654752f));
    h[(size_t)r * 128 + j] = g;
}

// ---------------- input LN + pos add -> ubig si columns --------------------
__global__ void k_ln_in(const float* __restrict__ x,
                        const float* __restrict__ pos2,
                        const float* __restrict__ lnw, const float* __restrict__ lnb,
                        const float* __restrict__ pb2,
                        float* __restrict__ ubig)
{
    int r = blockIdx.x, t = threadIdx.x;   // 256 threads
    const float* xr = x + (size_t)r * DD;
    float v0 = xr[t], v1 = xr[t + 256];
    __shared__ float sh[256];
    __shared__ float s_mean, s_rstd;
    sh[t] = v0 + v1;
    __syncthreads();
    for (int o = 128; o > 0; o >>= 1) { if (t < o) sh[t] += sh[t + o]; __syncthreads(); }
    if (t == 0) s_mean = sh[0] * (1.f / 512.f);
    __syncthreads();
    float m = s_mean;
    float d0 = v0 - m, d1 = v1 - m;
    sh[t] = d0 * d0 + d1 * d1;
    __syncthreads();
    for (int o = 128; o > 0; o >>= 1) { if (t < o) sh[t] += sh[t + o]; __syncthreads(); }
    if (t == 0) s_rstd = rsqrtf(sh[0] * (1.f / 512.f) + 1e-6f);
    __syncthreads();
    float rs = s_rstd;
    const float* pr = pos2 + (size_t)r * DD;
    float* u = ubig + (size_t)r * UCOLS + 1024;
    u[t]       = d0 * rs * lnw[t]       + lnb[t]       + pr[t]       + pb2[t];
    u[t + 256] = d1 * rs * lnw[t + 256] + lnb[t + 256] + pr[t + 256] + pb2[t + 256];
}

// ---------------- conv+silu + proj + delta ("prep") ------------------------
__global__ __launch_bounds__(256) void k_prep(
    const float* __restrict__ xz,
    const float* __restrict__ cxw, const float* __restrict__ czw,
    const float* __restrict__ xpw,
    const float* __restrict__ dtw, const float* __restrict__ dtb,
    float* __restrict__ delta, float* __restrict__ xb_out,
    float* __restrict__ btg, float* __restrict__ ctg,
    float* __restrict__ ubig, int d)
{
    int r = blockIdx.x;
    int l = r & (LL - 1);
    int t = threadIdx.x;
    __shared__ float sxb[256];
    __shared__ float sproj[48];
    size_t row = (size_t)r * DD;
    float x0 = xz[row + t];
    float z0 = xz[row + 256 + t];
    float xm = 0.f, xp = 0.f, zm = 0.f, zp = 0.f;
    if (l > 0)      { xm = xz[row - DD + t]; zm = xz[row - DD + 256 + t]; }
    if (l < LL - 1) { xp = xz[row + DD + t]; zp = xz[row + DD + 256 + t]; }
    const float* cw = cxw + (size_t)(d * II + t) * 3;
    const float* zw = czw + (size_t)(d * II + t) * 3;
    float xc, zc;
    if (d == 0) {
        xc = cw[0] * xm + cw[1] * x0 + cw[2] * xp;
        zc = zw[0] * zm + zw[1] * z0 + zw[2] * zp;
    } else {  // flipped sequence => reversed taps
        xc = cw[0] * xp + cw[1] * x0 + cw[2] * xm;
        zc = zw[0] * zp + zw[1] * z0 + zw[2] * zm;
    }
    float xbv = xc / (1.f + __expf(-xc));
    float zbv = zc / (1.f + __expf(-zc));
    sxb[t] = xbv;
    xb_out[(size_t)(d * ROWS + r) * II + t] = xbv;
    ubig[(size_t)r * UCOLS + (d ? 768 : 256) + t] = zbv;
    __syncthreads();

    int warp = t >> 5, lane = t & 31;
    #pragma unroll
    for (int jj = 0; jj < 6; jj++) {
        int j = warp * 6 + jj;    // 8 warps x 6 = 48 outputs
        const float* wr = xpw + (size_t)(d * 48 + j) * II;
        float p = 0.f;
        #pragma unroll
        for (int kk = 0; kk < 8; kk++)
            p = fmaf(sxb[lane + kk * 32], wr[lane + kk * 32], p);
        #pragma unroll
        for (int o = 16; o > 0; o >>= 1) p += __shfl_xor_sync(0xffffffffu, p, o);
        if (lane == 0) sproj[j] = p;
    }
    __syncthreads();

    if (t < 8) {
        btg[(size_t)(d * ROWS + r) * SS + t] = tanhf(sproj[32 + t]);
        ctg[(size_t)(d * ROWS + r) * SS + t] = tanhf(sproj[40 + t]);
    }
    float acc = dtb[d * II + t];
    const float* dwr = dtw + (size_t)(d * II + t) * DTR;
    #pragma unroll
    for (int k = 0; k < DTR; k++) acc = fmaf(sproj[k], dwr[k], acc);
    float sp = (acc > 20.f) ? acc : log1pf(expf(acc));
    sp = fminf(fmaxf(sp, 1e-4f), 1.0f);
    delta[(size_t)(d * ROWS + r) * II + t] = sp;
}

// ---------------- sequential selective scan --------------------------------
// one thread per (dir, b, i, s); width-8 shfl reduce over s; writes y into ubig.
__global__ __launch_bounds__(256) void k_scan(
    const float* __restrict__ delta, const float* __restrict__ xb,
    const float* __restrict__ bt, const float* __restrict__ ct,
    const float* __restrict__ Alog, const float* __restrict__ Dp,
    float* __restrict__ ubig)
{
    int tid = blockIdx.x * 256 + threadIdx.x;   // 0..32767
    int s = tid & 7;
    int chain = tid >> 3;
    int i = chain & (II - 1);
    int b = (chain >> 8) & (BB - 1);
    int d = chain >> 11;

    float a = log1pf(expf(Alog[(size_t)(d * II + i) * SS + s])) + 1e-4f;
    float dp = Dp[d * II + i];

    long baseDX = ((long)d * ROWS + (long)b * LL) * II + i;
    long baseBC = ((long)d * ROWS + (long)b * LL) * SS + s;
    long baseU  = (long)b * LL * UCOLS + (d ? 512 : 0) + i;

    int l0 = d ? (LL - 1) : 0;
    long sDX = d ? -(long)II : (long)II;
    long sBC = d ? -(long)SS : (long)SS;
    long sU  = d ? -(long)UCOLS : (long)UCOLS;
    long oDX = baseDX + (long)l0 * II;
    long oBC = baseBC + (long)l0 * SS;
    long oU  = baseU  + (long)l0 * UCOLS;

    float state = 0.f;
    for (int n = 0; n < LL; n++) {
        float dlt = delta[oDX];
        float xv  = xb[oDX];
        float btv = bt[oBC];
        float ctv = ct[oBC];
        float dec = __expf(-dlt * a);
        dec = fminf(fmaxf(dec, 1e-4f), 1.0f);
        state = fmaf(dec, state, (1.f - dec) * (btv * xv));
        float part = state * ctv;
        part += __shfl_xor_sync(0xffffffffu, part, 1);
        part += __shfl_xor_sync(0xffffffffu, part, 2);
        part += __shfl_xor_sync(0xffffffffu, part, 4);
        if (s == 0) ubig[oU] = part + dp * xv;
        oDX += sDX; oBC += sBC; oU += sU;
    }
}

// ---------------- output LN -------------------------------------------------
__global__ void k_ln_out(const float* __restrict__ mixed,
                         const float* __restrict__ w, const float* __restrict__ bias,
                         float* __restrict__ out)
{
    int r = blockIdx.x, t = threadIdx.x;
    const float* xr = mixed + (size_t)r * DD;
    float v0 = xr[t], v1 = xr[t + 256];
    __shared__ float sh[256];
    __shared__ float s_mean, s_rstd;
    sh[t] = v0 + v1;
    __syncthreads();
    for (int o = 128; o > 0; o >>= 1) { if (t < o) sh[t] += sh[t + o]; __syncthreads(); }
    if (t == 0) s_mean = sh[0] * (1.f / 512.f);
    __syncthreads();
    float m = s_mean;
    float d0 = v0 - m, d1 = v1 - m;
    sh[t] = d0 * d0 + d1 * d1;
    __syncthreads();
    for (int o = 128; o > 0; o >>= 1) { if (t < o) sh[t] += sh[t + o]; __syncthreads(); }
    if (t == 0) s_rstd = rsqrtf(sh[0] * (1.f / 512.f) + 1e-6f);
    __syncthreads();
    float rs = s_rstd;
    float* orow = out + (size_t)r * DD;
    orow[t]       = d0 * rs * w[t]       + bias[t];
    orow[t + 256] = d1 * rs * w[t + 256] + bias[t + 256];
}

// ---------------- host launch ----------------------------------------------
extern "C" void kernel_launch(void* const* d_in, const int* in_sizes, int n_in,
                              void* d_out, int out_size)
{
    const float* x        = (const float*)d_in[0];
    const float* position = (const float*)d_in[1];
    const float* ln_in_w  = (const float*)d_in[2];
    const float* ln_in_b  = (const float*)d_in[3];
    const float* pos_w1   = (const float*)d_in[4];
    const float* pos_b1   = (const float*)d_in[5];
    const float* pos_w2   = (const float*)d_in[6];
    const float* pos_b2   = (const float*)d_in[7];
    const float* in_w     = (const float*)d_in[8];
    const float* cx_w     = (const float*)d_in[9];
    const float* cz_w     = (const float*)d_in[10];
    const float* xp_w     = (const float*)d_in[11];
    const float* dt_w     = (const float*)d_in[12];
    const float* dt_b     = (const float*)d_in[13];
    const float* Alog     = (const float*)d_in[14];
    const float* Dp       = (const float*)d_in[15];
    const float* out_w    = (const float*)d_in[16];
    const float* mix_w    = (const float*)d_in[17];
    const float* ln_out_w = (const float*)d_in[18];
    const float* ln_out_b = (const float*)d_in[19];
    float* out = (float*)d_out;

    float *p_h, *p_pos, *p_ubig, *p_xz, *p_delta, *p_xbuf, *p_bt, *p_ct,
          *p_mixed, *p_owT, *p_wbig;
    cudaGetSymbolAddress((void**)&p_h,     g_h);
    cudaGetSymbolAddress((void**)&p_pos,   g_pos);
    cudaGetSymbolAddress((void**)&p_ubig,  g_ubig);
    cudaGetSymbolAddress((void**)&p_xz,    g_xz);
    cudaGetSymbolAddress((void**)&p_delta, g_delta);
    cudaGetSymbolAddress((void**)&p_xbuf,  g_xbuf);
    cudaGetSymbolAddress((void**)&p_bt,    g_bt);
    cudaGetSymbolAddress((void**)&p_ct,    g_ct);
    cudaGetSymbolAddress((void**)&p_mixed, g_mixed);
    cudaGetSymbolAddress((void**)&p_owT,   g_owT);
    cudaGetSymbolAddress((void**)&p_wbig,  g_wbig);

    // 1) fold out_w into mix_w:  W_f = mix_w[:,0:512] @ out_w[0],  W_b likewise
    k_transpose<<<dim3(16, 16, 2), dim3(32, 32)>>>(out_w, p_owT);
    // W_f: C[n,j] = sum_k mix_w[n,k] * owT0[j,k]
    sgemm_tn<<<dim3(8, 4), 256>>>(mix_w,        UCOLS, p_owT,            DD,
                                  p_wbig,       UCOLS, DD);
    sgemm_tn<<<dim3(8, 4), 256>>>(mix_w + 512,  UCOLS, p_owT + DD * DD,  DD,
                                  p_wbig + 512, UCOLS, DD);
    k_copytail<<<1024, 256>>>(mix_w, p_wbig);

    // 2) position MLP
    k_pos_h<<<ROWS, 128>>>(position, pos_w1, pos_b1, p_h);
    sgemm_tn<<<dim3(8, 128), 256>>>(p_h, 128, pos_w2, 128, p_pos, DD, 128);

    // 3) LN(x) + pos -> ubig[:,1024:1536]
    k_ln_in<<<ROWS, 256>>>(x, p_pos, ln_in_w, ln_in_b, pos_b2, p_ubig);

    // 4) per-direction: in-proj GEMM + prep
    for (int d = 0; d < 2; d++) {
        sgemm_tn<<<dim3(8, 128), 256>>>(p_ubig + 1024, UCOLS,
                                        in_w + (size_t)d * DD * DD, DD,
                                        p_xz, DD, DD);
        k_prep<<<ROWS, 256>>>(p_xz, cx_w, cz_w, xp_w, dt_w, dt_b,
                              p_delta, p_xbuf, p_bt, p_ct, p_ubig, d);
    }

    // 5) both scans (32768 threads)
    k_scan<<<128, 256>>>(p_delta, p_xbuf, p_bt, p_ct, Alog, Dp, p_ubig);

    // 6) fused out-proj + mix GEMM (K=1536)
    sgemm_tn<<<dim3(8, 128), 256>>>(p_ubig, UCOLS, p_wbig, UCOLS,
                                    p_mixed, DD, UCOLS);

    // 7) output LN
    k_ln_out<<<ROWS, 256>>>(p_mixed, ln_out_w, ln_out_b, out);
}

// round 4
// speedup vs baseline: 1.3572x; 1.3572x over previous
#include <cuda_runtime.h>
#include <cuda_bf16.h>
#include <cstdint>

// Problem constants
#define BB 8
#define LL 2048
#define DD 512
#define II 256
#define SS 8
#define DTR 32
#define ROWS (BB*LL)          // 16384
#define UCOLS 1536

// ---------------- scratch (static device globals; no runtime alloc) -------
__device__ float g_h    [ROWS * 128];        // pos hidden
__device__ float g_pos  [ROWS * DD];         // pos MLP output
__device__ float g_ubig [ROWS * UCOLS];      // [y_f, zb_f, y_b, zb_b, si]
__device__ float g_xz   [ROWS * DD];         // in-proj output (reused per dir)
__device__ float g_delta[2 * ROWS * II];
__device__ float g_xbuf [2 * ROWS * II];
__device__ float g_bt   [2 * ROWS * SS];
__device__ float g_ct   [2 * ROWS * SS];
__device__ float g_mixed[ROWS * DD];
__device__ float g_owT  [2 * DD * DD];       // transposed scan_out_w
__device__ float g_wbig [DD * UCOLS];        // folded mix weight [512,1536]

// ---------------- tf32 helpers ---------------------------------------------
__device__ __forceinline__ uint32_t f2tf32(float f) {
    uint32_t r;
    asm("cvt.rna.tf32.f32 %0, %1;" : "=r"(r) : "f"(f));
    return r;
}

#define MMA_TF32(d, a, b) \
    asm volatile("mma.sync.aligned.m16n8k8.row.col.f32.tf32.tf32.f32 " \
        "{%0,%1,%2,%3}, {%4,%5,%6,%7}, {%8,%9}, {%0,%1,%2,%3};" \
        : "+f"(d[0]), "+f"(d[1]), "+f"(d[2]), "+f"(d[3]) \
        : "r"(a[0]), "r"(a[1]), "r"(a[2]), "r"(a[3]), "r"(b[0]), "r"(b[1]))

// ---------------- tensor-core tf32 GEMM: C[m,n] = sum_k A[m,k]*W[n,k] ------
// BM=128, BN=128, BK=16, 256 threads (8 warps, 2x4 -> warp tile 64x32).
// Double-buffered smem, tf32 rounding applied at staging store.
// Requires: M%128==0, N%128==0, K%16==0, lda/ldw multiples of 4.
__global__ __launch_bounds__(256) void gemm_tf32(
    const float* __restrict__ A, int lda,
    const float* __restrict__ W, int ldw,
    float* __restrict__ C, int ldc, int K)
{
    __shared__ uint32_t As[2][128][20];   // padded stride 20 -> conflict-free
    __shared__ uint32_t Ws[2][128][20];
    const int bm = blockIdx.y * 128;
    const int bn = blockIdx.x * 128;
    const int tid = threadIdx.x;
    const int lane = tid & 31;
    const int wid = tid >> 5;
    const int wm = (wid & 1) * 64;        // warp M offset
    const int wn = (wid >> 1) * 32;       // warp N offset
    const int gr = lane >> 2;             // fragment row group 0..7
    const int gc = lane & 3;              // fragment col group 0..3

    float acc[4][4][4];
    #pragma unroll
    for (int mf = 0; mf < 4; mf++)
        #pragma unroll
        for (int nf = 0; nf < 4; nf++)
            #pragma unroll
            for (int e = 0; e < 4; e++) acc[mf][nf][e] = 0.f;

    const int rowL = tid >> 2;            // 0..63
    const int c4 = (tid & 3) * 4;         // 0,4,8,12
    const int nk = K >> 4;

    // prologue: stage tile 0
    #pragma unroll
    for (int u = 0; u < 2; u++) {
        int r = rowL + u * 64;
        float4 va = *reinterpret_cast<const float4*>(&A[(size_t)(bm + r) * lda + c4]);
        float4 vw = *reinterpret_cast<const float4*>(&W[(size_t)(bn + r) * ldw + c4]);
        uint4 ua = make_uint4(f2tf32(va.x), f2tf32(va.y), f2tf32(va.z), f2tf32(va.w));
        uint4 uw = make_uint4(f2tf32(vw.x), f2tf32(vw.y), f2tf32(vw.z), f2tf32(vw.w));
        *reinterpret_cast<uint4*>(&As[0][r][c4]) = ua;
        *reinterpret_cast<uint4*>(&Ws[0][r][c4]) = uw;
    }
    __syncthreads();

    for (int kt = 0; kt < nk; kt++) {
        const int p = kt & 1;
        float4 va[2], vw[2];
        if (kt + 1 < nk) {
            int k0 = (kt + 1) << 4;
            #pragma unroll
            for (int u = 0; u < 2; u++) {
                int r = rowL + u * 64;
                va[u] = *reinterpret_cast<const float4*>(&A[(size_t)(bm + r) * lda + k0 + c4]);
                vw[u] = *reinterpret_cast<const float4*>(&W[(size_t)(bn + r) * ldw + k0 + c4]);
            }
        }
        #pragma unroll
        for (int ks = 0; ks < 16; ks += 8) {
            uint32_t af[4][4];
            #pragma unroll
            for (int mf = 0; mf < 4; mf++) {
                int r = wm + mf * 16 + gr;
                int c = ks + gc;
                af[mf][0] = As[p][r][c];
                af[mf][1] = As[p][r + 8][c];
                af[mf][2] = As[p][r][c + 4];
                af[mf][3] = As[p][r + 8][c + 4];
            }
            uint32_t bf[4][2];
            #pragma unroll
            for (int nf = 0; nf < 4; nf++) {
                int r = wn + nf * 8 + gr;
                int c = ks + gc;
                bf[nf][0] = Ws[p][r][c];
                bf[nf][1] = Ws[p][r][c + 4];
            }
            #pragma unroll
            for (int mf = 0; mf < 4; mf++)
                #pragma unroll
                for (int nf = 0; nf < 4; nf++)
                    MMA_TF32(acc[mf][nf], af[mf], bf[nf]);
        }
        if (kt + 1 < nk) {
            const int q = 1 - p;
            #pragma unroll
            for (int u = 0; u < 2; u++) {
                int r = rowL + u * 64;
                uint4 ua = make_uint4(f2tf32(va[u].x), f2tf32(va[u].y),
                                      f2tf32(va[u].z), f2tf32(va[u].w));
                uint4 uw = make_uint4(f2tf32(vw[u].x), f2tf32(vw[u].y),
                                      f2tf32(vw[u].z), f2tf32(vw[u].w));
                *reinterpret_cast<uint4*>(&As[q][r][c4]) = ua;
                *reinterpret_cast<uint4*>(&Ws[q][r][c4]) = uw;
            }
        }
        __syncthreads();
    }

    // epilogue
    #pragma unroll
    for (int mf = 0; mf < 4; mf++) {
        #pragma unroll
        for (int nf = 0; nf < 4; nf++) {
            int r0 = bm + wm + mf * 16 + gr;
            int cc = bn + wn + nf * 8 + gc * 2;
            float2 v01 = make_float2(acc[mf][nf][0], acc[mf][nf][1]);
            float2 v23 = make_float2(acc[mf][nf][2], acc[mf][nf][3]);
            *reinterpret_cast<float2*>(&C[(size_t)r0 * ldc + cc]) = v01;
            *reinterpret_cast<float2*>(&C[(size_t)(r0 + 8) * ldc + cc]) = v23;
        }
    }
}

// ---------------- fp32 SGEMM (kept for the exact weight fold) --------------
__global__ __launch_bounds__(256) void sgemm_tn(
    const float* __restrict__ A, int lda,
    const float* __restrict__ W, int ldw,
    float* __restrict__ C, int ldc, int K)
{
    __shared__ float As[16][128];
    __shared__ float Ws[16][64];
    const int bm = blockIdx.y * 128;
    const int bn = blockIdx.x * 64;
    const int tid = threadIdx.x;
    const int tx = tid & 15;
    const int ty = tid >> 4;
    float acc[8][4];
    #pragma unroll
    for (int m = 0; m < 8; m++)
        #pragma unroll
        for (int n = 0; n < 4; n++) acc[m][n] = 0.f;

    for (int k0 = 0; k0 < K; k0 += 16) {
        #pragma unroll
        for (int u = 0; u < 2; u++) {
            int f = tid + u * 256;
            int row = f >> 2;
            int kk = (f & 3) * 4;
            float4 v = *reinterpret_cast<const float4*>(
                &A[(size_t)(bm + row) * lda + k0 + kk]);
            As[kk + 0][row] = v.x; As[kk + 1][row] = v.y;
            As[kk + 2][row] = v.z; As[kk + 3][row] = v.w;
        }
        {
            int row = tid >> 2;
            int kk = (tid & 3) * 4;
            float4 v = *reinterpret_cast<const float4*>(
                &W[(size_t)(bn + row) * ldw + k0 + kk]);
            Ws[kk + 0][row] = v.x; Ws[kk + 1][row] = v.y;
            Ws[kk + 2][row] = v.z; Ws[kk + 3][row] = v.w;
        }
        __syncthreads();
        #pragma unroll
        for (int kk = 0; kk < 16; kk++) {
            float af[8], wf[4];
            #pragma unroll
            for (int m = 0; m < 8; m++) af[m] = As[kk][ty * 8 + m];
            #pragma unroll
            for (int n = 0; n < 4; n++) wf[n] = Ws[kk][tx * 4 + n];
            #pragma unroll
            for (int m = 0; m < 8; m++)
                #pragma unroll
                for (int n = 0; n < 4; n++)
                    acc[m][n] = fmaf(af[m], wf[n], acc[m][n]);
        }
        __syncthreads();
    }
    #pragma unroll
    for (int m = 0; m < 8; m++) {
        float4 v = make_float4(acc[m][0], acc[m][1], acc[m][2], acc[m][3]);
        *reinterpret_cast<float4*>(
            &C[(size_t)(bm + ty * 8 + m) * ldc + bn + tx * 4]) = v;
    }
}

// ---------------- transpose 512x512 (per dir) ------------------------------
__global__ void k_transpose(const float* __restrict__ src, float* __restrict__ dst)
{
    __shared__ float tile[32][33];
    int d = blockIdx.z;
    src += (size_t)d * DD * DD;
    dst += (size_t)d * DD * DD;
    int x = blockIdx.x * 32 + threadIdx.x;
    int y = blockIdx.y * 32 + threadIdx.y;
    tile[threadIdx.y][threadIdx.x] = src[(size_t)y * DD + x];
    __syncthreads();
    x = blockIdx.y * 32 + threadIdx.x;
    y = blockIdx.x * 32 + threadIdx.y;
    dst[(size_t)y * DD + x] = tile[threadIdx.x][threadIdx.y];
}

// copy mix_w[:,1024:1536] into g_wbig[:,1024:1536]
__global__ void k_copytail(const float* __restrict__ mixw, float* __restrict__ wbig)
{
    int idx = blockIdx.x * 256 + threadIdx.x;   // 0..262143
    int n = idx >> 9, j = idx & 511;
    wbig[(size_t)n * UCOLS + 1024 + j] = mixw[(size_t)n * UCOLS + 1024 + j];
}

// ---------------- position MLP layer 1 (6 -> 128, exact GELU) --------------
__global__ void k_pos_h(const float* __restrict__ position,
                        const float* __restrict__ pw1,
                        const float* __restrict__ pb1,
                        float* __restrict__ h)
{
    int r = blockIdx.x, j = threadIdx.x;      // 128 threads
    __shared__ float p[6];
    if (j < 6) p[j] = position[(size_t)r * 6 + j];
    __syncthreads();
    float acc = pb1[j];
    #pragma unroll
    for (int c = 0; c < 6; c++) acc = fmaf(pw1[j * 6 + c], p[c], acc);
    float g = 0.5f * acc * (1.f + erff(acc * 0.70710678118654752f));
    h[(size_t)r * 128 + j] = g;
}

// ---------------- input LN + pos add -> ubig si columns --------------------
__global__ void k_ln_in(const float* __restrict__ x,
                        const float* __restrict__ pos2,
                        const float* __restrict__ lnw, const float* __restrict__ lnb,
                        const float* __restrict__ pb2,
                        float* __restrict__ ubig)
{
    int r = blockIdx.x, t = threadIdx.x;   // 256 threads
    const float* xr = x + (size_t)r * DD;
    float v0 = xr[t], v1 = xr[t + 256];
    __shared__ float sh[256];
    __shared__ float s_mean, s_rstd;
    sh[t] = v0 + v1;
    __syncthreads();
    for (int o = 128; o > 0; o >>= 1) { if (t < o) sh[t] += sh[t + o]; __syncthreads(); }
    if (t == 0) s_mean = sh[0] * (1.f / 512.f);
    __syncthreads();
    float m = s_mean;
    float d0 = v0 - m, d1 = v1 - m;
    sh[t] = d0 * d0 + d1 * d1;
    __syncthreads();
    for (int o = 128; o > 0; o >>= 1) { if (t < o) sh[t] += sh[t + o]; __syncthreads(); }
    if (t == 0) s_rstd = rsqrtf(sh[0] * (1.f / 512.f) + 1e-6f);
    __syncthreads();
    float rs = s_rstd;
    const float* pr = pos2 + (size_t)r * DD;
    float* u = ubig + (size_t)r * UCOLS + 1024;
    u[t]       = d0 * rs * lnw[t]       + lnb[t]       + pr[t]       + pb2[t];
    u[t + 256] = d1 * rs * lnw[t + 256] + lnb[t + 256] + pr[t + 256] + pb2[t + 256];
}

// ---------------- conv+silu + proj + delta ("prep") ------------------------
__global__ __launch_bounds__(256) void k_prep(
    const float* __restrict__ xz,
    const float* __restrict__ cxw, const float* __restrict__ czw,
    const float* __restrict__ xpw,
    const float* __restrict__ dtw, const float* __restrict__ dtb,
    float* __restrict__ delta, float* __restrict__ xb_out,
    float* __restrict__ btg, float* __restrict__ ctg,
    float* __restrict__ ubig, int d)
{
    int r = blockIdx.x;
    int l = r & (LL - 1);
    int t = threadIdx.x;
    __shared__ float sxb[256];
    __shared__ float sproj[48];
    size_t row = (size_t)r * DD;
    float x0 = xz[row + t];
    float z0 = xz[row + 256 + t];
    float xm = 0.f, xp = 0.f, zm = 0.f, zp = 0.f;
    if (l > 0)      { xm = xz[row - DD + t]; zm = xz[row - DD + 256 + t]; }
    if (l < LL - 1) { xp = xz[row + DD + t]; zp = xz[row + DD + 256 + t]; }
    const float* cw = cxw + (size_t)(d * II + t) * 3;
    const float* zw = czw + (size_t)(d * II + t) * 3;
    float xc, zc;
    if (d == 0) {
        xc = cw[0] * xm + cw[1] * x0 + cw[2] * xp;
        zc = zw[0] * zm + zw[1] * z0 + zw[2] * zp;
    } else {  // flipped sequence => reversed taps
        xc = cw[0] * xp + cw[1] * x0 + cw[2] * xm;
        zc = zw[0] * zp + zw[1] * z0 + zw[2] * zm;
    }
    float xbv = xc / (1.f + __expf(-xc));
    float zbv = zc / (1.f + __expf(-zc));
    sxb[t] = xbv;
    xb_out[(size_t)(d * ROWS + r) * II + t] = xbv;
    ubig[(size_t)r * UCOLS + (d ? 768 : 256) + t] = zbv;
    __syncthreads();

    int warp = t >> 5, lane = t & 31;
    #pragma unroll
    for (int jj = 0; jj < 6; jj++) {
        int j = warp * 6 + jj;    // 8 warps x 6 = 48 outputs
        const float* wr = xpw + (size_t)(d * 48 + j) * II;
        float p = 0.f;
        #pragma unroll
        for (int kk = 0; kk < 8; kk++)
            p = fmaf(sxb[lane + kk * 32], wr[lane + kk * 32], p);
        #pragma unroll
        for (int o = 16; o > 0; o >>= 1) p += __shfl_xor_sync(0xffffffffu, p, o);
        if (lane == 0) sproj[j] = p;
    }
    __syncthreads();

    if (t < 8) {
        btg[(size_t)(d * ROWS + r) * SS + t] = tanhf(sproj[32 + t]);
        ctg[(size_t)(d * ROWS + r) * SS + t] = tanhf(sproj[40 + t]);
    }
    float acc = dtb[d * II + t];
    const float* dwr = dtw + (size_t)(d * II + t) * DTR;
    #pragma unroll
    for (int k = 0; k < DTR; k++) acc = fmaf(sproj[k], dwr[k], acc);
    float sp = (acc > 20.f) ? acc : log1pf(expf(acc));
    sp = fminf(fmaxf(sp, 1e-4f), 1.0f);
    delta[(size_t)(d * ROWS + r) * II + t] = sp;
}

// ---------------- sequential selective scan --------------------------------
__global__ __launch_bounds__(256) void k_scan(
    const float* __restrict__ delta, const float* __restrict__ xb,
    const float* __restrict__ bt, const float* __restrict__ ct,
    const float* __restrict__ Alog, const float* __restrict__ Dp,
    float* __restrict__ ubig)
{
    int tid = blockIdx.x * 256 + threadIdx.x;   // 0..32767
    int s = tid & 7;
    int chain = tid >> 3;
    int i = chain & (II - 1);
    int b = (chain >> 8) & (BB - 1);
    int d = chain >> 11;

    float a = log1pf(expf(Alog[(size_t)(d * II + i) * SS + s])) + 1e-4f;
    float dp = Dp[d * II + i];

    long baseDX = ((long)d * ROWS + (long)b * LL) * II + i;
    long baseBC = ((long)d * ROWS + (long)b * LL) * SS + s;
    long baseU  = (long)b * LL * UCOLS + (d ? 512 : 0) + i;

    int l0 = d ? (LL - 1) : 0;
    long sDX = d ? -(long)II : (long)II;
    long sBC = d ? -(long)SS : (long)SS;
    long sU  = d ? -(long)UCOLS : (long)UCOLS;
    long oDX = baseDX + (long)l0 * II;
    long oBC = baseBC + (long)l0 * SS;
    long oU  = baseU  + (long)l0 * UCOLS;

    float state = 0.f;
    for (int n = 0; n < LL; n++) {
        float dlt = delta[oDX];
        float xv  = xb[oDX];
        float btv = bt[oBC];
        float ctv = ct[oBC];
        float dec = __expf(-dlt * a);
        dec = fminf(fmaxf(dec, 1e-4f), 1.0f);
        state = fmaf(dec, state, (1.f - dec) * (btv * xv));
        float part = state * ctv;
        part += __shfl_xor_sync(0xffffffffu, part, 1);
        part += __shfl_xor_sync(0xffffffffu, part, 2);
        part += __shfl_xor_sync(0xffffffffu, part, 4);
        if (s == 0) ubig[oU] = part + dp * xv;
        oDX += sDX; oBC += sBC; oU += sU;
    }
}

// ---------------- output LN -------------------------------------------------
__global__ void k_ln_out(const float* __restrict__ mixed,
                         const float* __restrict__ w, const float* __restrict__ bias,
                         float* __restrict__ out)
{
    int r = blockIdx.x, t = threadIdx.x;
    const float* xr = mixed + (size_t)r * DD;
    float v0 = xr[t], v1 = xr[t + 256];
    __shared__ float sh[256];
    __shared__ float s_mean, s_rstd;
    sh[t] = v0 + v1;
    __syncthreads();
    for (int o = 128; o > 0; o >>= 1) { if (t < o) sh[t] += sh[t + o]; __syncthreads(); }
    if (t == 0) s_mean = sh[0] * (1.f / 512.f);
    __syncthreads();
    float m = s_mean;
    float d0 = v0 - m, d1 = v1 - m;
    sh[t] = d0 * d0 + d1 * d1;
    __syncthreads();
    for (int o = 128; o > 0; o >>= 1) { if (t < o) sh[t] += sh[t + o]; __syncthreads(); }
    if (t == 0) s_rstd = rsqrtf(sh[0] * (1.f / 512.f) + 1e-6f);
    __syncthreads();
    float rs = s_rstd;
    float* orow = out + (size_t)r * DD;
    orow[t]       = d0 * rs * w[t]       + bias[t];
    orow[t + 256] = d1 * rs * w[t + 256] + bias[t + 256];
}

// ---------------- host launch ----------------------------------------------
extern "C" void kernel_launch(void* const* d_in, const int* in_sizes, int n_in,
                              void* d_out, int out_size)
{
    const float* x        = (const float*)d_in[0];
    const float* position = (const float*)d_in[1];
    const float* ln_in_w  = (const float*)d_in[2];
    const float* ln_in_b  = (const float*)d_in[3];
    const float* pos_w1   = (const float*)d_in[4];
    const float* pos_b1   = (const float*)d_in[5];
    const float* pos_w2   = (const float*)d_in[6];
    const float* pos_b2   = (const float*)d_in[7];
    const float* in_w     = (const float*)d_in[8];
    const float* cx_w     = (const float*)d_in[9];
    const float* cz_w     = (const float*)d_in[10];
    const float* xp_w     = (const float*)d_in[11];
    const float* dt_w     = (const float*)d_in[12];
    const float* dt_b     = (const float*)d_in[13];
    const float* Alog     = (const float*)d_in[14];
    const float* Dp       = (const float*)d_in[15];
    const float* out_w    = (const float*)d_in[16];
    const float* mix_w    = (const float*)d_in[17];
    const float* ln_out_w = (const float*)d_in[18];
    const float* ln_out_b = (const float*)d_in[19];
    float* out = (float*)d_out;

    float *p_h, *p_pos, *p_ubig, *p_xz, *p_delta, *p_xbuf, *p_bt, *p_ct,
          *p_mixed, *p_owT, *p_wbig;
    cudaGetSymbolAddress((void**)&p_h,     g_h);
    cudaGetSymbolAddress((void**)&p_pos,   g_pos);
    cudaGetSymbolAddress((void**)&p_ubig,  g_ubig);
    cudaGetSymbolAddress((void**)&p_xz,    g_xz);
    cudaGetSymbolAddress((void**)&p_delta, g_delta);
    cudaGetSymbolAddress((void**)&p_xbuf,  g_xbuf);
    cudaGetSymbolAddress((void**)&p_bt,    g_bt);
    cudaGetSymbolAddress((void**)&p_ct,    g_ct);
    cudaGetSymbolAddress((void**)&p_mixed, g_mixed);
    cudaGetSymbolAddress((void**)&p_owT,   g_owT);
    cudaGetSymbolAddress((void**)&p_wbig,  g_wbig);

    // 1) position MLP (tf32 tensor GEMM for layer 2)
    k_pos_h<<<ROWS, 128>>>(position, pos_w1, pos_b1, p_h);
    gemm_tf32<<<dim3(4, 128), 256>>>(p_h, 128, pos_w2, 128, p_pos, DD, 128);

    // 2) LN(x) + pos -> ubig[:,1024:1536]
    k_ln_in<<<ROWS, 256>>>(x, p_pos, ln_in_w, ln_in_b, pos_b2, p_ubig);

    // 3) per-direction: in-proj GEMM (tf32) + prep
    for (int d = 0; d < 2; d++) {
        gemm_tf32<<<dim3(4, 128), 256>>>(p_ubig + 1024, UCOLS,
                                         in_w + (size_t)d * DD * DD, DD,
                                         p_xz, DD, DD);
        k_prep<<<ROWS, 256>>>(p_xz, cx_w, cz_w, xp_w, dt_w, dt_b,
                              p_delta, p_xbuf, p_bt, p_ct, p_ubig, d);
    }

    // 4) fold out_w into mix_w in exact fp32 (independent of 1-3; needed by 6)
    k_transpose<<<dim3(16, 16, 2), dim3(32, 32)>>>(out_w, p_owT);
    sgemm_tn<<<dim3(8, 4), 256>>>(mix_w,        UCOLS, p_owT,            DD,
                                  p_wbig,       UCOLS, DD);
    sgemm_tn<<<dim3(8, 4), 256>>>(mix_w + 512,  UCOLS, p_owT + DD * DD,  DD,
                                  p_wbig + 512, UCOLS, DD);
    k_copytail<<<1024, 256>>>(mix_w, p_wbig);

    // 5) both scans (32768 threads)
    k_scan<<<128, 256>>>(p_delta, p_xbuf, p_bt, p_ct, Alog, Dp, p_ubig);

    // 6) fused out-proj + mix GEMM (tf32, K=1536)
    gemm_tf32<<<dim3(4, 128), 256>>>(p_ubig, UCOLS, p_wbig, UCOLS,
                                     p_mixed, DD, UCOLS);

    // 7) output LN
    k_ln_out<<<ROWS, 256>>>(p_mixed, ln_out_w, ln_out_b, out);
}

// round 7
// speedup vs baseline: 4.8648x; 3.5845x over previous
#include <cuda_runtime.h>
#include <cuda_bf16.h>
#include <cstdint>

// Problem constants
#define BB 8
#define LL 2048
#define DD 512
#define II 256
#define SS 8
#define DTR 32
#define ROWS (BB*LL)          // 16384
#define UCOLS 1536

// ---------------- scratch (static device globals; no runtime alloc) -------
__device__ float  g_h    [ROWS * 128];       // pos hidden
__device__ float  g_pos  [ROWS * DD];        // pos MLP output
__device__ float  g_ubig [ROWS * UCOLS];     // [y_f, zb_f, y_b, zb_b, si]
__device__ float  g_xz0  [ROWS * DD];        // in-proj output dir 0
__device__ float  g_xz1  [ROWS * DD];        // in-proj output dir 1
__device__ float2 g_dx   [2 * ROWS * II];    // (delta, xb) pairs
__device__ float2 g_bc   [2 * ROWS * SS];    // (bt, ct) pairs
__device__ float  g_mixed[ROWS * DD];
__device__ float  g_owT  [2 * DD * DD];      // transposed scan_out_w
__device__ float  g_wbig [DD * UCOLS];       // folded mix weight [512,1536]

// ---------------- tf32 helpers ---------------------------------------------
__device__ __forceinline__ uint32_t f2tf32(float f) {
    uint32_t r;
    asm("cvt.rna.tf32.f32 %0, %1;" : "=r"(r) : "f"(f));
    return r;
}

#define MMA_TF32(d, a, b) \
    asm volatile("mma.sync.aligned.m16n8k8.row.col.f32.tf32.tf32.f32 " \
        "{%0,%1,%2,%3}, {%4,%5,%6,%7}, {%8,%9}, {%0,%1,%2,%3};" \
        : "+f"(d[0]), "+f"(d[1]), "+f"(d[2]), "+f"(d[3]) \
        : "r"(a[0]), "r"(a[1]), "r"(a[2]), "r"(a[3]), "r"(b[0]), "r"(b[1]))

// ---------------- tensor-core tf32 GEMM: C[m,n] = sum_k A[m,k]*W[n,k] ------
__global__ __launch_bounds__(256) void gemm_tf32(
    const float* __restrict__ A, int lda,
    const float* __restrict__ W, int ldw,
    float* __restrict__ C, int ldc, int K)
{
    __shared__ uint32_t As[2][128][20];
    __shared__ uint32_t Ws[2][128][20];
    const int bm = blockIdx.y * 128;
    const int bn = blockIdx.x * 128;
    const int tid = threadIdx.x;
    const int lane = tid & 31;
    const int wid = tid >> 5;
    const int wm = (wid & 1) * 64;
    const int wn = (wid >> 1) * 32;
    const int gr = lane >> 2;
    const int gc = lane & 3;

    float acc[4][4][4];
    #pragma unroll
    for (int mf = 0; mf < 4; mf++)
        #pragma unroll
        for (int nf = 0; nf < 4; nf++)
            #pragma unroll
            for (int e = 0; e < 4; e++) acc[mf][nf][e] = 0.f;

    const int rowL = tid >> 2;
    const int c4 = (tid & 3) * 4;
    const int nk = K >> 4;

    #pragma unroll
    for (int u = 0; u < 2; u++) {
        int r = rowL + u * 64;
        float4 va = *reinterpret_cast<const float4*>(&A[(size_t)(bm + r) * lda + c4]);
        float4 vw = *reinterpret_cast<const float4*>(&W[(size_t)(bn + r) * ldw + c4]);
        uint4 ua = make_uint4(f2tf32(va.x), f2tf32(va.y), f2tf32(va.z), f2tf32(va.w));
        uint4 uw = make_uint4(f2tf32(vw.x), f2tf32(vw.y), f2tf32(vw.z), f2tf32(vw.w));
        *reinterpret_cast<uint4*>(&As[0][r][c4]) = ua;
        *reinterpret_cast<uint4*>(&Ws[0][r][c4]) = uw;
    }
    __syncthreads();

    for (int kt = 0; kt < nk; kt++) {
        const int p = kt & 1;
        float4 va[2], vw[2];
        if (kt + 1 < nk) {
            int k0 = (kt + 1) << 4;
            #pragma unroll
            for (int u = 0; u < 2; u++) {
                int r = rowL + u * 64;
                va[u] = *reinterpret_cast<const float4*>(&A[(size_t)(bm + r) * lda + k0 + c4]);
                vw[u] = *reinterpret_cast<const float4*>(&W[(size_t)(bn + r) * ldw + k0 + c4]);
            }
        }
        #pragma unroll
        for (int ks = 0; ks < 16; ks += 8) {
            uint32_t af[4][4];
            #pragma unroll
            for (int mf = 0; mf < 4; mf++) {
                int r = wm + mf * 16 + gr;
                int c = ks + gc;
                af[mf][0] = As[p][r][c];
                af[mf][1] = As[p][r + 8][c];
                af[mf][2] = As[p][r][c + 4];
                af[mf][3] = As[p][r + 8][c + 4];
            }
            uint32_t bf[4][2];
            #pragma unroll
            for (int nf = 0; nf < 4; nf++) {
                int r = wn + nf * 8 + gr;
                int c = ks + gc;
                bf[nf][0] = Ws[p][r][c];
                bf[nf][1] = Ws[p][r][c + 4];
            }
            #pragma unroll
            for (int mf = 0; mf < 4; mf++)
                #pragma unroll
                for (int nf = 0; nf < 4; nf++)
                    MMA_TF32(acc[mf][nf], af[mf], bf[nf]);
        }
        if (kt + 1 < nk) {
            const int q = 1 - p;
            #pragma unroll
            for (int u = 0; u < 2; u++) {
                int r = rowL + u * 64;
                uint4 ua = make_uint4(f2tf32(va[u].x), f2tf32(va[u].y),
                                      f2tf32(va[u].z), f2tf32(va[u].w));
                uint4 uw = make_uint4(f2tf32(vw[u].x), f2tf32(vw[u].y),
                                      f2tf32(vw[u].z), f2tf32(vw[u].w));
                *reinterpret_cast<uint4*>(&As[q][r][c4]) = ua;
                *reinterpret_cast<uint4*>(&Ws[q][r][c4]) = uw;
            }
        }
        __syncthreads();
    }

    #pragma unroll
    for (int mf = 0; mf < 4; mf++) {
        #pragma unroll
        for (int nf = 0; nf < 4; nf++) {
            int r0 = bm + wm + mf * 16 + gr;
            int cc = bn + wn + nf * 8 + gc * 2;
            float2 v01 = make_float2(acc[mf][nf][0], acc[mf][nf][1]);
            float2 v23 = make_float2(acc[mf][nf][2], acc[mf][nf][3]);
            *reinterpret_cast<float2*>(&C[(size_t)r0 * ldc + cc]) = v01;
            *reinterpret_cast<float2*>(&C[(size_t)(r0 + 8) * ldc + cc]) = v23;
        }
    }
}

// ---------------- fp32 SGEMM (exact weight fold) ---------------------------
__global__ __launch_bounds__(256) void sgemm_tn(
    const float* __restrict__ A, int lda,
    const float* __restrict__ W, int ldw,
    float* __restrict__ C, int ldc, int K)
{
    __shared__ float As[16][128];
    __shared__ float Ws[16][64];
    const int bm = blockIdx.y * 128;
    const int bn = blockIdx.x * 64;
    const int tid = threadIdx.x;
    const int tx = tid & 15;
    const int ty = tid >> 4;
    float acc[8][4];
    #pragma unroll
    for (int m = 0; m < 8; m++)
        #pragma unroll
        for (int n = 0; n < 4; n++) acc[m][n] = 0.f;

    for (int k0 = 0; k0 < K; k0 += 16) {
        #pragma unroll
        for (int u = 0; u < 2; u++) {
            int f = tid + u * 256;
            int row = f >> 2;
            int kk = (f & 3) * 4;
            float4 v = *reinterpret_cast<const float4*>(
                &A[(size_t)(bm + row) * lda + k0 + kk]);
            As[kk + 0][row] = v.x; As[kk + 1][row] = v.y;
            As[kk + 2][row] = v.z; As[kk + 3][row] = v.w;
        }
        {
            int row = tid >> 2;
            int kk = (tid & 3) * 4;
            float4 v = *reinterpret_cast<const float4*>(
                &W[(size_t)(bn + row) * ldw + k0 + kk]);
            Ws[kk + 0][row] = v.x; Ws[kk + 1][row] = v.y;
            Ws[kk + 2][row] = v.z; Ws[kk + 3][row] = v.w;
        }
        __syncthreads();
        #pragma unroll
        for (int kk = 0; kk < 16; kk++) {
            float af[8], wf[4];
            #pragma unroll
            for (int m = 0; m < 8; m++) af[m] = As[kk][ty * 8 + m];
            #pragma unroll
            for (int n = 0; n < 4; n++) wf[n] = Ws[kk][tx * 4 + n];
            #pragma unroll
            for (int m = 0; m < 8; m++)
                #pragma unroll
                for (int n = 0; n < 4; n++)
                    acc[m][n] = fmaf(af[m], wf[n], acc[m][n]);
        }
        __syncthreads();
    }
    #pragma unroll
    for (int m = 0; m < 8; m++) {
        float4 v = make_float4(acc[m][0], acc[m][1], acc[m][2], acc[m][3]);
        *reinterpret_cast<float4*>(
            &C[(size_t)(bm + ty * 8 + m) * ldc + bn + tx * 4]) = v;
    }
}

// ---------------- transpose 512x512 (per dir) ------------------------------
__global__ void k_transpose(const float* __restrict__ src, float* __restrict__ dst)
{
    __shared__ float tile[32][33];
    int d = blockIdx.z;
    src += (size_t)d * DD * DD;
    dst += (size_t)d * DD * DD;
    int x = blockIdx.x * 32 + threadIdx.x;
    int y = blockIdx.y * 32 + threadIdx.y;
    tile[threadIdx.y][threadIdx.x] = src[(size_t)y * DD + x];
    __syncthreads();
    x = blockIdx.y * 32 + threadIdx.x;
    y = blockIdx.x * 32 + threadIdx.y;
    dst[(size_t)y * DD + x] = tile[threadIdx.x][threadIdx.y];
}

// copy mix_w[:,1024:1536] into g_wbig[:,1024:1536]
__global__ void k_copytail(const float* __restrict__ mixw, float* __restrict__ wbig)
{
    int idx = blockIdx.x * 256 + threadIdx.x;
    int n = idx >> 9, j = idx & 511;
    wbig[(size_t)n * UCOLS + 1024 + j] = mixw[(size_t)n * UCOLS + 1024 + j];
}

// ---------------- position MLP layer 1 (6 -> 128, exact GELU) --------------
__global__ void k_pos_h(const float* __restrict__ position,
                        const float* __restrict__ pw1,
                        const float* __restrict__ pb1,
                        float* __restrict__ h)
{
    int r = blockIdx.x, j = threadIdx.x;
    __shared__ float p[6];
    if (j < 6) p[j] = position[(size_t)r * 6 + j];
    __syncthreads();
    float acc = pb1[j];
    #pragma unroll
    for (int c = 0; c < 6; c++) acc = fmaf(pw1[j * 6 + c], p[c], acc);
    float g = 0.5f * acc * (1.f + erff(acc * 0.70710678118654752f));
    h[(size_t)r * 128 + j] = g;
}

// ---------------- block reduce helper (256 threads) ------------------------
__device__ __forceinline__ float block_sum256(float v, float* sw, int t)
{
    #pragma unroll
    for (int o = 16; o > 0; o >>= 1) v += __shfl_xor_sync(0xffffffffu, v, o);
    if ((t & 31) == 0) sw[t >> 5] = v;
    __syncthreads();
    float r = sw[t & 7];
    #pragma unroll
    for (int o = 4; o > 0; o >>= 1) r += __shfl_xor_sync(0xffffffffu, r, o);
    return r;   // valid in all threads (each reads one of 8 then reduces)
}

// ---------------- input LN + pos add -> ubig si columns --------------------
__global__ void k_ln_in(const float* __restrict__ x,
                        const float* __restrict__ pos2,
                        const float* __restrict__ lnw, const float* __restrict__ lnb,
                        const float* __restrict__ pb2,
                        float* __restrict__ ubig)
{
    int r = blockIdx.x, t = threadIdx.x;   // 256 threads
    const float* xr = x + (size_t)r * DD;
    float v0 = xr[t], v1 = xr[t + 256];
    __shared__ float sw[8];
    float total = block_sum256(v0 + v1, sw, t);
    float m = total * (1.f / 512.f);
    __syncthreads();
    float d0 = v0 - m, d1 = v1 - m;
    float vsum = block_sum256(d0 * d0 + d1 * d1, sw, t);
    float rs = rsqrtf(vsum * (1.f / 512.f) + 1e-6f);
    const float* pr = pos2 + (size_t)r * DD;
    float* u = ubig + (size_t)r * UCOLS + 1024;
    u[t]       = d0 * rs * lnw[t]       + lnb[t]       + pr[t]       + pb2[t];
    u[t + 256] = d1 * rs * lnw[t + 256] + lnb[t + 256] + pr[t + 256] + pb2[t + 256];
}

// ---------------- conv+silu + proj + delta ("prep"), both dirs -------------
__global__ __launch_bounds__(256) void k_prep(
    const float* __restrict__ xz0, const float* __restrict__ xz1,
    const float* __restrict__ cxw, const float* __restrict__ czw,
    const float* __restrict__ xpw,
    const float* __restrict__ dtw, const float* __restrict__ dtb,
    float2* __restrict__ dx, float2* __restrict__ bc,
    float* __restrict__ ubig)
{
    int r = blockIdx.x;
    int d = blockIdx.y;
    int l = r & (LL - 1);
    int t = threadIdx.x;
    const float* xz = d ? xz1 : xz0;
    __shared__ float sxb[256];
    __shared__ float sproj[48];
    __shared__ float sdt[256 * 33];    // padded dt_w rows

    // coalesced stage of dt_w[d] (256x32 floats) into padded smem
    {
        const float4* dtg = reinterpret_cast<const float4*>(dtw + (size_t)d * II * DTR);
        #pragma unroll
        for (int u = 0; u < 8; u++) {
            int f = t + u * 256;            // float4 index 0..2047
            float4 v = dtg[f];
            int tr = f >> 3;                // row
            int kc = (f & 7) * 4;           // col
            sdt[tr * 33 + kc + 0] = v.x;
            sdt[tr * 33 + kc + 1] = v.y;
            sdt[tr * 33 + kc + 2] = v.z;
            sdt[tr * 33 + kc + 3] = v.w;
        }
    }

    size_t row = (size_t)r * DD;
    float x0 = xz[row + t];
    float z0 = xz[row + 256 + t];
    float xm = 0.f, xp = 0.f, zm = 0.f, zp = 0.f;
    if (l > 0)      { xm = xz[row - DD + t]; zm = xz[row - DD + 256 + t]; }
    if (l < LL - 1) { xp = xz[row + DD + t]; zp = xz[row + DD + 256 + t]; }
    const float* cw = cxw + (size_t)(d * II + t) * 3;
    const float* zw = czw + (size_t)(d * II + t) * 3;
    float xc, zc;
    if (d == 0) {
        xc = cw[0] * xm + cw[1] * x0 + cw[2] * xp;
        zc = zw[0] * zm + zw[1] * z0 + zw[2] * zp;
    } else {
        xc = cw[0] * xp + cw[1] * x0 + cw[2] * xm;
        zc = zw[0] * zp + zw[1] * z0 + zw[2] * zm;
    }
    float xbv = xc / (1.f + __expf(-xc));
    float zbv = zc / (1.f + __expf(-zc));
    sxb[t] = xbv;
    ubig[(size_t)r * UCOLS + (d ? 768 : 256) + t] = zbv;
    __syncthreads();

    int warp = t >> 5, lane = t & 31;
    #pragma unroll
    for (int jj = 0; jj < 6; jj++) {
        int j = warp * 6 + jj;
        const float* wr = xpw + (size_t)(d * 48 + j) * II;
        float p = 0.f;
        #pragma unroll
        for (int kk = 0; kk < 8; kk++)
            p = fmaf(sxb[lane + kk * 32], wr[lane + kk * 32], p);
        #pragma unroll
        for (int o = 16; o > 0; o >>= 1) p += __shfl_xor_sync(0xffffffffu, p, o);
        if (lane == 0) sproj[j] = p;
    }
    __syncthreads();

    if (t < 8) {
        bc[(size_t)(d * ROWS + r) * SS + t] =
            make_float2(tanhf(sproj[32 + t]), tanhf(sproj[40 + t]));
    }
    float acc = dtb[d * II + t];
    const float* sr = &sdt[t * 33];
    #pragma unroll
    for (int k = 0; k < DTR; k++) acc = fmaf(sproj[k], sr[k], acc);
    float sp = (acc > 20.f) ? acc : log1pf(expf(acc));
    sp = fminf(fmaxf(sp, 1e-4f), 1.0f);
    dx[(size_t)(d * ROWS + r) * II + t] = make_float2(sp, xbv);
}

// ---------------- sequential selective scan (batched prefetch) -------------
__global__ __launch_bounds__(256) void k_scan(
    const float2* __restrict__ dx, const float2* __restrict__ bc,
    const float* __restrict__ Alog, const float* __restrict__ Dp,
    float* __restrict__ ubig)
{
    int tid = blockIdx.x * 256 + threadIdx.x;   // 0..32767
    int s = tid & 7;
    int chain = tid >> 3;
    int i = chain & (II - 1);
    int b = (chain >> 8) & (BB - 1);
    int d = chain >> 11;

    float a = log1pf(expf(Alog[(d * II + i) * SS + s])) + 1e-4f;
    float dp = Dp[d * II + i];

    int l0  = d ? (LL - 1) : 0;
    int sDX = d ? -II : II;
    int sBC = d ? -SS : SS;
    int sU  = d ? -UCOLS : UCOLS;
    int oDX = (d * ROWS + b * LL + l0) * II + i;
    int oBC = (d * ROWS + b * LL + l0) * SS + s;
    int oU  = b * LL * UCOLS + (d ? 512 : 0) + i + l0 * UCOLS;

    float state = 0.f;
    float2 cd[8], cb[8];
    #pragma unroll
    for (int u = 0; u < 8; u++) {
        cd[u] = dx[oDX + u * sDX];
        cb[u] = bc[oBC + u * sBC];
    }
    for (int n0 = 0; n0 < LL; n0 += 8) {
        float2 nd[8], nb[8];
        bool more = (n0 + 8 < LL);
        if (more) {
            int p1 = oDX + 8 * sDX;
            int p2 = oBC + 8 * sBC;
            #pragma unroll
            for (int u = 0; u < 8; u++) {
                nd[u] = dx[p1 + u * sDX];
                nb[u] = bc[p2 + u * sBC];
            }
        }
        #pragma unroll
        for (int u = 0; u < 8; u++) {
            float dec = __expf(-cd[u].x * a);
            dec = fminf(fmaxf(dec, 1e-4f), 1.0f);
            state = fmaf(dec, state, (1.f - dec) * (cb[u].x * cd[u].y));
            float part = state * cb[u].y;
            part += __shfl_xor_sync(0xffffffffu, part, 1);
            part += __shfl_xor_sync(0xffffffffu, part, 2);
            part += __shfl_xor_sync(0xffffffffu, part, 4);
            if (s == 0) ubig[oU + u * sU] = part + dp * cd[u].y;
        }
        if (more) {
            #pragma unroll
            for (int u = 0; u < 8; u++) { cd[u] = nd[u]; cb[u] = nb[u]; }
        }
        oDX += 8 * sDX; oBC += 8 * sBC; oU += 8 * sU;
    }
}

// ---------------- output LN -------------------------------------------------
__global__ void k_ln_out(const float* __restrict__ mixed,
                         const float* __restrict__ w, const float* __restrict__ bias,
                         float* __restrict__ out)
{
    int r = blockIdx.x, t = threadIdx.x;
    const float* xr = mixed + (size_t)r * DD;
    float v0 = xr[t], v1 = xr[t + 256];
    __shared__ float sw[8];
    float total = block_sum256(v0 + v1, sw, t);
    float m = total * (1.f / 512.f);
    __syncthreads();
    float d0 = v0 - m, d1 = v1 - m;
    float vsum = block_sum256(d0 * d0 + d1 * d1, sw, t);
    float rs = rsqrtf(vsum * (1.f / 512.f) + 1e-6f);
    float* orow = out + (size_t)r * DD;
    orow[t]       = d0 * rs * w[t]       + bias[t];
    orow[t + 256] = d1 * rs * w[t + 256] + bias[t + 256];
}

// ---------------- host launch ----------------------------------------------
extern "C" void kernel_launch(void* const* d_in, const int* in_sizes, int n_in,
                              void* d_out, int out_size)
{
    const float* x        = (const float*)d_in[0];
    const float* position = (const float*)d_in[1];
    const float* ln_in_w  = (const float*)d_in[2];
    const float* ln_in_b  = (const float*)d_in[3];
    const float* pos_w1   = (const float*)d_in[4];
    const float* pos_b1   = (const float*)d_in[5];
    const float* pos_w2   = (const float*)d_in[6];
    const float* pos_b2   = (const float*)d_in[7];
    const float* in_w     = (const float*)d_in[8];
    const float* cx_w     = (const float*)d_in[9];
    const float* cz_w     = (const float*)d_in[10];
    const float* xp_w     = (const float*)d_in[11];
    const float* dt_w     = (const float*)d_in[12];
    const float* dt_b     = (const float*)d_in[13];
    const float* Alog     = (const float*)d_in[14];
    const float* Dp       = (const float*)d_in[15];
    const float* out_w    = (const float*)d_in[16];
    const float* mix_w    = (const float*)d_in[17];
    const float* ln_out_w = (const float*)d_in[18];
    const float* ln_out_b = (const float*)d_in[19];
    float* out = (float*)d_out;

    float  *p_h, *p_pos, *p_ubig, *p_xz0, *p_xz1, *p_mixed, *p_owT, *p_wbig;
    float2 *p_dx, *p_bc;
    cudaGetSymbolAddress((void**)&p_h,     g_h);
    cudaGetSymbolAddress((void**)&p_pos,   g_pos);
    cudaGetSymbolAddress((void**)&p_ubig,  g_ubig);
    cudaGetSymbolAddress((void**)&p_xz0,   g_xz0);
    cudaGetSymbolAddress((void**)&p_xz1,   g_xz1);
    cudaGetSymbolAddress((void**)&p_dx,    g_dx);
    cudaGetSymbolAddress((void**)&p_bc,    g_bc);
    cudaGetSymbolAddress((void**)&p_mixed, g_mixed);
    cudaGetSymbolAddress((void**)&p_owT,   g_owT);
    cudaGetSymbolAddress((void**)&p_wbig,  g_wbig);

    // 1) position MLP
    k_pos_h<<<ROWS, 128>>>(position, pos_w1, pos_b1, p_h);            // launch 1
    gemm_tf32<<<dim3(4, 128), 256>>>(p_h, 128, pos_w2, 128,
                                     p_pos, DD, 128);                 // launch 2

    // 2) LN(x) + pos -> ubig si columns
    k_ln_in<<<ROWS, 256>>>(x, p_pos, ln_in_w, ln_in_b, pos_b2,
                           p_ubig);                                   // launch 3

    // 3) in-proj GEMMs (both dirs), then fused prep (captured by ncu: #6)
    gemm_tf32<<<dim3(4, 128), 256>>>(p_ubig + 1024, UCOLS, in_w, DD,
                                     p_xz0, DD, DD);                  // launch 4
    gemm_tf32<<<dim3(4, 128), 256>>>(p_ubig + 1024, UCOLS,
                                     in_w + (size_t)DD * DD, DD,
                                     p_xz1, DD, DD);                  // launch 5
    k_prep<<<dim3(ROWS, 2), 256>>>(p_xz0, p_xz1, cx_w, cz_w, xp_w,
                                   dt_w, dt_b, p_dx, p_bc, p_ubig);   // launch 6

    // 4) fold out_w into mix_w in exact fp32
    k_transpose<<<dim3(16, 16, 2), dim3(32, 32)>>>(out_w, p_owT);
    sgemm_tn<<<dim3(8, 4), 256>>>(mix_w,        UCOLS, p_owT,            DD,
                                  p_wbig,       UCOLS, DD);
    sgemm_tn<<<dim3(8, 4), 256>>>(mix_w + 512,  UCOLS, p_owT + DD * DD,  DD,
                                  p_wbig + 512, UCOLS, DD);
    k_copytail<<<1024, 256>>>(mix_w, p_wbig);

    // 5) both scans
    k_scan<<<128, 256>>>(p_dx, p_bc, Alog, Dp, p_ubig);

    // 6) fused out-proj + mix GEMM (tf32, K=1536)
    gemm_tf32<<<dim3(4, 128), 256>>>(p_ubig, UCOLS, p_wbig, UCOLS,
                                     p_mixed, DD, UCOLS);

    // 7) output LN
    k_ln_out<<<ROWS, 256>>>(p_mixed, ln_out_w, ln_out_b, out);
}

// round 8
// speedup vs baseline: 5.0518x; 1.0384x over previous
#include <cuda_runtime.h>
#include <cuda_bf16.h>
#include <cstdint>

// Problem constants
#define BB 8
#define LL 2048
#define DD 512
#define II 256
#define SS 8
#define DTR 32
#define ROWS (BB*LL)          // 16384
#define UCOLS 1536
#define RPER 16               // rows per k_prep block

// ---------------- scratch (static device globals; no runtime alloc) -------
__device__ float  g_h    [ROWS * 128];       // pos hidden
__device__ float  g_pos  [ROWS * DD];        // pos MLP output
__device__ float  g_ubig [ROWS * UCOLS];     // [y_f, zb_f, y_b, zb_b, si]
__device__ float  g_xzc  [ROWS * 1024];      // fused in-proj output (both dirs)
__device__ float2 g_dx   [2 * ROWS * II];    // (delta, xb) pairs
__device__ float2 g_bc   [2 * ROWS * SS];    // (bt, ct) pairs
__device__ float  g_mixed[ROWS * DD];
__device__ float  g_owT  [2 * DD * DD];      // transposed scan_out_w
__device__ float  g_wbig [DD * UCOLS];       // folded mix weight [512,1536]

// ---------------- tf32 helpers ---------------------------------------------
__device__ __forceinline__ uint32_t f2tf32(float f) {
    uint32_t r;
    asm("cvt.rna.tf32.f32 %0, %1;" : "=r"(r) : "f"(f));
    return r;
}

#define MMA_TF32(d, a, b) \
    asm volatile("mma.sync.aligned.m16n8k8.row.col.f32.tf32.tf32.f32 " \
        "{%0,%1,%2,%3}, {%4,%5,%6,%7}, {%8,%9}, {%0,%1,%2,%3};" \
        : "+f"(d[0]), "+f"(d[1]), "+f"(d[2]), "+f"(d[3]) \
        : "r"(a[0]), "r"(a[1]), "r"(a[2]), "r"(a[3]), "r"(b[0]), "r"(b[1]))

// ---------------- tensor-core tf32 GEMM: C[m,n] = sum_k A[m,k]*W[n,k] ------
__global__ __launch_bounds__(256) void gemm_tf32(
    const float* __restrict__ A, int lda,
    const float* __restrict__ W, int ldw,
    float* __restrict__ C, int ldc, int K)
{
    __shared__ uint32_t As[2][128][20];
    __shared__ uint32_t Ws[2][128][20];
    const int bm = blockIdx.y * 128;
    const int bn = blockIdx.x * 128;
    const int tid = threadIdx.x;
    const int lane = tid & 31;
    const int wid = tid >> 5;
    const int wm = (wid & 1) * 64;
    const int wn = (wid >> 1) * 32;
    const int gr = lane >> 2;
    const int gc = lane & 3;

    float acc[4][4][4];
    #pragma unroll
    for (int mf = 0; mf < 4; mf++)
        #pragma unroll
        for (int nf = 0; nf < 4; nf++)
            #pragma unroll
            for (int e = 0; e < 4; e++) acc[mf][nf][e] = 0.f;

    const int rowL = tid >> 2;
    const int c4 = (tid & 3) * 4;
    const int nk = K >> 4;

    #pragma unroll
    for (int u = 0; u < 2; u++) {
        int r = rowL + u * 64;
        float4 va = *reinterpret_cast<const float4*>(&A[(size_t)(bm + r) * lda + c4]);
        float4 vw = *reinterpret_cast<const float4*>(&W[(size_t)(bn + r) * ldw + c4]);
        uint4 ua = make_uint4(f2tf32(va.x), f2tf32(va.y), f2tf32(va.z), f2tf32(va.w));
        uint4 uw = make_uint4(f2tf32(vw.x), f2tf32(vw.y), f2tf32(vw.z), f2tf32(vw.w));
        *reinterpret_cast<uint4*>(&As[0][r][c4]) = ua;
        *reinterpret_cast<uint4*>(&Ws[0][r][c4]) = uw;
    }
    __syncthreads();

    for (int kt = 0; kt < nk; kt++) {
        const int p = kt & 1;
        float4 va[2], vw[2];
        if (kt + 1 < nk) {
            int k0 = (kt + 1) << 4;
            #pragma unroll
            for (int u = 0; u < 2; u++) {
                int r = rowL + u * 64;
                va[u] = *reinterpret_cast<const float4*>(&A[(size_t)(bm + r) * lda + k0 + c4]);
                vw[u] = *reinterpret_cast<const float4*>(&W[(size_t)(bn + r) * ldw + k0 + c4]);
            }
        }
        #pragma unroll
        for (int ks = 0; ks < 16; ks += 8) {
            uint32_t af[4][4];
            #pragma unroll
            for (int mf = 0; mf < 4; mf++) {
                int r = wm + mf * 16 + gr;
                int c = ks + gc;
                af[mf][0] = As[p][r][c];
                af[mf][1] = As[p][r + 8][c];
                af[mf][2] = As[p][r][c + 4];
                af[mf][3] = As[p][r + 8][c + 4];
            }
            uint32_t bf[4][2];
            #pragma unroll
            for (int nf = 0; nf < 4; nf++) {
                int r = wn + nf * 8 + gr;
                int c = ks + gc;
                bf[nf][0] = Ws[p][r][c];
                bf[nf][1] = Ws[p][r][c + 4];
            }
            #pragma unroll
            for (int mf = 0; mf < 4; mf++)
                #pragma unroll
                for (int nf = 0; nf < 4; nf++)
                    MMA_TF32(acc[mf][nf], af[mf], bf[nf]);
        }
        if (kt + 1 < nk) {
            const int q = 1 - p;
            #pragma unroll
            for (int u = 0; u < 2; u++) {
                int r = rowL + u * 64;
                uint4 ua = make_uint4(f2tf32(va[u].x), f2tf32(va[u].y),
                                      f2tf32(va[u].z), f2tf32(va[u].w));
                uint4 uw = make_uint4(f2tf32(vw[u].x), f2tf32(vw[u].y),
                                      f2tf32(vw[u].z), f2tf32(vw[u].w));
                *reinterpret_cast<uint4*>(&As[q][r][c4]) = ua;
                *reinterpret_cast<uint4*>(&Ws[q][r][c4]) = uw;
            }
        }
        __syncthreads();
    }

    #pragma unroll
    for (int mf = 0; mf < 4; mf++) {
        #pragma unroll
        for (int nf = 0; nf < 4; nf++) {
            int r0 = bm + wm + mf * 16 + gr;
            int cc = bn + wn + nf * 8 + gc * 2;
            float2 v01 = make_float2(acc[mf][nf][0], acc[mf][nf][1]);
            float2 v23 = make_float2(acc[mf][nf][2], acc[mf][nf][3]);
            *reinterpret_cast<float2*>(&C[(size_t)r0 * ldc + cc]) = v01;
            *reinterpret_cast<float2*>(&C[(size_t)(r0 + 8) * ldc + cc]) = v23;
        }
    }
}

// ---------------- fp32 SGEMM (exact weight fold) ---------------------------
__global__ __launch_bounds__(256) void sgemm_tn(
    const float* __restrict__ A, int lda,
    const float* __restrict__ W, int ldw,
    float* __restrict__ C, int ldc, int K)
{
    __shared__ float As[16][128];
    __shared__ float Ws[16][64];
    const int bm = blockIdx.y * 128;
    const int bn = blockIdx.x * 64;
    const int tid = threadIdx.x;
    const int tx = tid & 15;
    const int ty = tid >> 4;
    float acc[8][4];
    #pragma unroll
    for (int m = 0; m < 8; m++)
        #pragma unroll
        for (int n = 0; n < 4; n++) acc[m][n] = 0.f;

    for (int k0 = 0; k0 < K; k0 += 16) {
        #pragma unroll
        for (int u = 0; u < 2; u++) {
            int f = tid + u * 256;
            int row = f >> 2;
            int kk = (f & 3) * 4;
            float4 v = *reinterpret_cast<const float4*>(
                &A[(size_t)(bm + row) * lda + k0 + kk]);
            As[kk + 0][row] = v.x; As[kk + 1][row] = v.y;
            As[kk + 2][row] = v.z; As[kk + 3][row] = v.w;
        }
        {
            int row = tid >> 2;
            int kk = (tid & 3) * 4;
            float4 v = *reinterpret_cast<const float4*>(
                &W[(size_t)(bn + row) * ldw + k0 + kk]);
            Ws[kk + 0][row] = v.x; Ws[kk + 1][row] = v.y;
            Ws[kk + 2][row] = v.z; Ws[kk + 3][row] = v.w;
        }
        __syncthreads();
        #pragma unroll
        for (int kk = 0; kk < 16; kk++) {
            float af[8], wf[4];
            #pragma unroll
            for (int m = 0; m < 8; m++) af[m] = As[kk][ty * 8 + m];
            #pragma unroll
            for (int n = 0; n < 4; n++) wf[n] = Ws[kk][tx * 4 + n];
            #pragma unroll
            for (int m = 0; m < 8; m++)
                #pragma unroll
                for (int n = 0; n < 4; n++)
                    acc[m][n] = fmaf(af[m], wf[n], acc[m][n]);
        }
        __syncthreads();
    }
    #pragma unroll
    for (int m = 0; m < 8; m++) {
        float4 v = make_float4(acc[m][0], acc[m][1], acc[m][2], acc[m][3]);
        *reinterpret_cast<float4*>(
            &C[(size_t)(bm + ty * 8 + m) * ldc + bn + tx * 4]) = v;
    }
}

// ---------------- transpose 512x512 (per dir) ------------------------------
__global__ void k_transpose(const float* __restrict__ src, float* __restrict__ dst)
{
    __shared__ float tile[32][33];
    int d = blockIdx.z;
    src += (size_t)d * DD * DD;
    dst += (size_t)d * DD * DD;
    int x = blockIdx.x * 32 + threadIdx.x;
    int y = blockIdx.y * 32 + threadIdx.y;
    tile[threadIdx.y][threadIdx.x] = src[(size_t)y * DD + x];
    __syncthreads();
    x = blockIdx.y * 32 + threadIdx.x;
    y = blockIdx.x * 32 + threadIdx.y;
    dst[(size_t)y * DD + x] = tile[threadIdx.x][threadIdx.y];
}

// copy mix_w[:,1024:1536] into g_wbig[:,1024:1536]
__global__ void k_copytail(const float* __restrict__ mixw, float* __restrict__ wbig)
{
    int idx = blockIdx.x * 256 + threadIdx.x;
    int n = idx >> 9, j = idx & 511;
    wbig[(size_t)n * UCOLS + 1024 + j] = mixw[(size_t)n * UCOLS + 1024 + j];
}

// ---------------- position MLP layer 1 (6 -> 128, exact GELU) --------------
__global__ void k_pos_h(const float* __restrict__ position,
                        const float* __restrict__ pw1,
                        const float* __restrict__ pb1,
                        float* __restrict__ h)
{
    int r = blockIdx.x, j = threadIdx.x;
    __shared__ float p[6];
    if (j < 6) p[j] = position[(size_t)r * 6 + j];
    __syncthreads();
    float acc = pb1[j];
    #pragma unroll
    for (int c = 0; c < 6; c++) acc = fmaf(pw1[j * 6 + c], p[c], acc);
    float g = 0.5f * acc * (1.f + erff(acc * 0.70710678118654752f));
    h[(size_t)r * 128 + j] = g;
}

// ---------------- block reduce helper (256 threads) ------------------------
__device__ __forceinline__ float block_sum256(float v, float* sw, int t)
{
    #pragma unroll
    for (int o = 16; o > 0; o >>= 1) v += __shfl_xor_sync(0xffffffffu, v, o);
    if ((t & 31) == 0) sw[t >> 5] = v;
    __syncthreads();
    float r = sw[t & 7];
    #pragma unroll
    for (int o = 4; o > 0; o >>= 1) r += __shfl_xor_sync(0xffffffffu, r, o);
    return r;
}

// ---------------- input LN + pos add -> ubig si columns --------------------
__global__ void k_ln_in(const float* __restrict__ x,
                        const float* __restrict__ pos2,
                        const float* __restrict__ lnw, const float* __restrict__ lnb,
                        const float* __restrict__ pb2,
                        float* __restrict__ ubig)
{
    int r = blockIdx.x, t = threadIdx.x;
    const float* xr = x + (size_t)r * DD;
    float v0 = xr[t], v1 = xr[t + 256];
    __shared__ float sw[8];
    float total = block_sum256(v0 + v1, sw, t);
    float m = total * (1.f / 512.f);
    __syncthreads();
    float d0 = v0 - m, d1 = v1 - m;
    float vsum = block_sum256(d0 * d0 + d1 * d1, sw, t);
    float rs = rsqrtf(vsum * (1.f / 512.f) + 1e-6f);
    const float* pr = pos2 + (size_t)r * DD;
    float* u = ubig + (size_t)r * UCOLS + 1024;
    u[t]       = d0 * rs * lnw[t]       + lnb[t]       + pr[t]       + pb2[t];
    u[t + 256] = d1 * rs * lnw[t + 256] + lnb[t + 256] + pr[t + 256] + pb2[t + 256];
}

// ---------------- conv+silu + proj + delta ("prep"), blocked over rows -----
// grid (ROWS/RPER, 2). Stages xp_w (48x256) and dt_w (256x32, padded) into
// dynamic smem ONCE per block, reused for RPER rows.
__global__ __launch_bounds__(256) void k_prep(
    const float* __restrict__ xzc,     // [ROWS][1024], dir d at cols d*512
    const float* __restrict__ cxw, const float* __restrict__ czw,
    const float* __restrict__ xpw,
    const float* __restrict__ dtw, const float* __restrict__ dtb,
    float2* __restrict__ dx, float2* __restrict__ bc,
    float* __restrict__ ubig)
{
    const int t = threadIdx.x;
    const int d = blockIdx.y;
    const int r0 = blockIdx.x * RPER;

    extern __shared__ float sm[];
    float* sxpw  = sm;                    // 48*256 = 12288
    float* sdt   = sm + 12288;            // 256*33 = 8448
    float* sxb   = sm + 12288 + 8448;     // 256
    float* sproj = sxb + 256;             // 48

    // stage xp_w[d] (48x256) coalesced
    {
        const float4* xg = reinterpret_cast<const float4*>(xpw + (size_t)d * 48 * II);
        #pragma unroll
        for (int u = 0; u < 12; u++)
            reinterpret_cast<float4*>(sxpw)[t + u * 256] = xg[t + u * 256];
    }
    // stage dt_w[d] (256x32) into padded rows
    {
        const float4* dtg = reinterpret_cast<const float4*>(dtw + (size_t)d * II * DTR);
        #pragma unroll
        for (int u = 0; u < 8; u++) {
            int f = t + u * 256;
            float4 v = dtg[f];
            int tr = f >> 3, kc = (f & 7) * 4;
            sdt[tr * 33 + kc + 0] = v.x;
            sdt[tr * 33 + kc + 1] = v.y;
            sdt[tr * 33 + kc + 2] = v.z;
            sdt[tr * 33 + kc + 3] = v.w;
        }
    }

    // per-thread conv weights / bias (hoisted)
    const float* cwp = cxw + (size_t)(d * II + t) * 3;
    const float* zwp = czw + (size_t)(d * II + t) * 3;
    float cw0 = cwp[0], cw1 = cwp[1], cw2 = cwp[2];
    float zw0 = zwp[0], zw1 = zwp[1], zw2 = zwp[2];
    float bias = dtb[d * II + t];
    const int warp = t >> 5, lane = t & 31;
    __syncthreads();

    for (int rr = 0; rr < RPER; rr++) {
        int r = r0 + rr;
        int l = r & (LL - 1);
        size_t row = (size_t)r * 1024 + d * 512;
        float x0 = xzc[row + t];
        float z0 = xzc[row + 256 + t];
        float xm = 0.f, xp = 0.f, zm = 0.f, zp = 0.f;
        if (l > 0)      { xm = xzc[row - 1024 + t]; zm = xzc[row - 1024 + 256 + t]; }
        if (l < LL - 1) { xp = xzc[row + 1024 + t]; zp = xzc[row + 1024 + 256 + t]; }
        float xc, zc;
        if (d == 0) {
            xc = cw0 * xm + cw1 * x0 + cw2 * xp;
            zc = zw0 * zm + zw1 * z0 + zw2 * zp;
        } else {
            xc = cw0 * xp + cw1 * x0 + cw2 * xm;
            zc = zw0 * zp + zw1 * z0 + zw2 * zm;
        }
        float xbv = xc / (1.f + __expf(-xc));
        float zbv = zc / (1.f + __expf(-zc));
        sxb[t] = xbv;
        ubig[(size_t)r * UCOLS + (d ? 768 : 256) + t] = zbv;
        __syncthreads();

        #pragma unroll
        for (int jj = 0; jj < 6; jj++) {
            int j = warp * 6 + jj;
            const float* wr = sxpw + j * 256;
            float p = 0.f;
            #pragma unroll
            for (int kk = 0; kk < 8; kk++)
                p = fmaf(sxb[lane + kk * 32], wr[lane + kk * 32], p);
            #pragma unroll
            for (int o = 16; o > 0; o >>= 1) p += __shfl_xor_sync(0xffffffffu, p, o);
            if (lane == 0) sproj[j] = p;
        }
        __syncthreads();

        if (t < 8) {
            bc[(size_t)(d * ROWS + r) * SS + t] =
                make_float2(tanhf(sproj[32 + t]), tanhf(sproj[40 + t]));
        }
        float acc = bias;
        const float* sr = &sdt[t * 33];
        #pragma unroll
        for (int k = 0; k < DTR; k++) acc = fmaf(sproj[k], sr[k], acc);
        float sp = (acc > 20.f) ? acc : log1pf(expf(acc));
        sp = fminf(fmaxf(sp, 1e-4f), 1.0f);
        dx[(size_t)(d * ROWS + r) * II + t] = make_float2(sp, xbv);
    }
}

// ---------------- sequential selective scan (batched prefetch) -------------
__global__ __launch_bounds__(256) void k_scan(
    const float2* __restrict__ dx, const float2* __restrict__ bc,
    const float* __restrict__ Alog, const float* __restrict__ Dp,
    float* __restrict__ ubig)
{
    int tid = blockIdx.x * 256 + threadIdx.x;   // 0..32767
    int s = tid & 7;
    int chain = tid >> 3;
    int i = chain & (II - 1);
    int b = (chain >> 8) & (BB - 1);
    int d = chain >> 11;

    float a = log1pf(expf(Alog[(d * II + i) * SS + s])) + 1e-4f;
    float dp = Dp[d * II + i];

    int l0  = d ? (LL - 1) : 0;
    int sDX = d ? -II : II;
    int sBC = d ? -SS : SS;
    int sU  = d ? -UCOLS : UCOLS;
    int oDX = (d * ROWS + b * LL + l0) * II + i;
    int oBC = (d * ROWS + b * LL + l0) * SS + s;
    int oU  = b * LL * UCOLS + (d ? 512 : 0) + i + l0 * UCOLS;

    float state = 0.f;
    float2 cd[8], cb[8];
    #pragma unroll
    for (int u = 0; u < 8; u++) {
        cd[u] = dx[oDX + u * sDX];
        cb[u] = bc[oBC + u * sBC];
    }
    for (int n0 = 0; n0 < LL; n0 += 8) {
        float2 nd[8], nb[8];
        bool more = (n0 + 8 < LL);
        if (more) {
            int p1 = oDX + 8 * sDX;
            int p2 = oBC + 8 * sBC;
            #pragma unroll
            for (int u = 0; u < 8; u++) {
                nd[u] = dx[p1 + u * sDX];
                nb[u] = bc[p2 + u * sBC];
            }
        }
        #pragma unroll
        for (int u = 0; u < 8; u++) {
            float dec = __expf(-cd[u].x * a);
            dec = fminf(fmaxf(dec, 1e-4f), 1.0f);
            state = fmaf(dec, state, (1.f - dec) * (cb[u].x * cd[u].y));
            float part = state * cb[u].y;
            part += __shfl_xor_sync(0xffffffffu, part, 1);
            part += __shfl_xor_sync(0xffffffffu, part, 2);
            part += __shfl_xor_sync(0xffffffffu, part, 4);
            if (s == 0) ubig[oU + u * sU] = part + dp * cd[u].y;
        }
        if (more) {
            #pragma unroll
            for (int u = 0; u < 8; u++) { cd[u] = nd[u]; cb[u] = nb[u]; }
        }
        oDX += 8 * sDX; oBC += 8 * sBC; oU += 8 * sU;
    }
}

// ---------------- output LN -------------------------------------------------
__global__ void k_ln_out(const float* __restrict__ mixed,
                         const float* __restrict__ w, const float* __restrict__ bias,
                         float* __restrict__ out)
{
    int r = blockIdx.x, t = threadIdx.x;
    const float* xr = mixed + (size_t)r * DD;
    float v0 = xr[t], v1 = xr[t + 256];
    __shared__ float sw[8];
    float total = block_sum256(v0 + v1, sw, t);
    float m = total * (1.f / 512.f);
    __syncthreads();
    float d0 = v0 - m, d1 = v1 - m;
    float vsum = block_sum256(d0 * d0 + d1 * d1, sw, t);
    float rs = rsqrtf(vsum * (1.f / 512.f) + 1e-6f);
    float* orow = out + (size_t)r * DD;
    orow[t]       = d0 * rs * w[t]       + bias[t];
    orow[t + 256] = d1 * rs * w[t + 256] + bias[t + 256];
}

// ---------------- host launch ----------------------------------------------
extern "C" void kernel_launch(void* const* d_in, const int* in_sizes, int n_in,
                              void* d_out, int out_size)
{
    const float* x        = (const float*)d_in[0];
    const float* position = (const float*)d_in[1];
    const float* ln_in_w  = (const float*)d_in[2];
    const float* ln_in_b  = (const float*)d_in[3];
    const float* pos_w1   = (const float*)d_in[4];
    const float* pos_b1   = (const float*)d_in[5];
    const float* pos_w2   = (const float*)d_in[6];
    const float* pos_b2   = (const float*)d_in[7];
    const float* in_w     = (const float*)d_in[8];
    const float* cx_w     = (const float*)d_in[9];
    const float* cz_w     = (const float*)d_in[10];
    const float* xp_w     = (const float*)d_in[11];
    const float* dt_w     = (const float*)d_in[12];
    const float* dt_b     = (const float*)d_in[13];
    const float* Alog     = (const float*)d_in[14];
    const float* Dp       = (const float*)d_in[15];
    const float* out_w    = (const float*)d_in[16];
    const float* mix_w    = (const float*)d_in[17];
    const float* ln_out_w = (const float*)d_in[18];
    const float* ln_out_b = (const float*)d_in[19];
    float* out = (float*)d_out;

    float  *p_h, *p_pos, *p_ubig, *p_xzc, *p_mixed, *p_owT, *p_wbig;
    float2 *p_dx, *p_bc;
    cudaGetSymbolAddress((void**)&p_h,     g_h);
    cudaGetSymbolAddress((void**)&p_pos,   g_pos);
    cudaGetSymbolAddress((void**)&p_ubig,  g_ubig);
    cudaGetSymbolAddress((void**)&p_xzc,   g_xzc);
    cudaGetSymbolAddress((void**)&p_dx,    g_dx);
    cudaGetSymbolAddress((void**)&p_bc,    g_bc);
    cudaGetSymbolAddress((void**)&p_mixed, g_mixed);
    cudaGetSymbolAddress((void**)&p_owT,   g_owT);
    cudaGetSymbolAddress((void**)&p_wbig,  g_wbig);

    // k_prep uses 84.2 KB dynamic smem
    const int prep_smem = (12288 + 8448 + 256 + 48) * 4;
    cudaFuncSetAttribute(k_prep, cudaFuncAttributeMaxDynamicSharedMemorySize,
                         prep_smem);

    // 1) position MLP
    k_pos_h<<<ROWS, 128>>>(position, pos_w1, pos_b1, p_h);          // L1
    gemm_tf32<<<dim3(4, 128), 256>>>(p_h, 128, pos_w2, 128,
                                     p_pos, DD, 128);               // L2

    // 2) LN(x) + pos -> ubig si columns
    k_ln_in<<<ROWS, 256>>>(x, p_pos, ln_in_w, ln_in_b, pos_b2,
                           p_ubig);                                 // L3

    // 3) fused in-proj GEMM (both dirs, N=1024), then blocked prep
    gemm_tf32<<<dim3(8, 128), 256>>>(p_ubig + 1024, UCOLS, in_w, DD,
                                     p_xzc, 1024, DD);              // L4
    k_prep<<<dim3(ROWS / RPER, 2), 256, prep_smem>>>(
        p_xzc, cx_w, cz_w, xp_w, dt_w, dt_b, p_dx, p_bc, p_ubig);   // L5

    // 4) both scans (ncu capture target: launch 6)
    k_scan<<<128, 256>>>(p_dx, p_bc, Alog, Dp, p_ubig);             // L6

    // 5) fold out_w into mix_w in exact fp32
    k_transpose<<<dim3(16, 16, 2), dim3(32, 32)>>>(out_w, p_owT);
    sgemm_tn<<<dim3(8, 4), 256>>>(mix_w,        UCOLS, p_owT,            DD,
                                  p_wbig,       UCOLS, DD);
    sgemm_tn<<<dim3(8, 4), 256>>>(mix_w + 512,  UCOLS, p_owT + DD * DD,  DD,
                                  p_wbig + 512, UCOLS, DD);
    k_copytail<<<1024, 256>>>(mix_w, p_wbig);

    // 6) fused out-proj + mix GEMM (tf32, K=1536)
    gemm_tf32<<<dim3(4, 128), 256>>>(p_ubig, UCOLS, p_wbig, UCOLS,
                                     p_mixed, DD, UCOLS);

    // 7) output LN
    k_ln_out<<<ROWS, 256>>>(p_mixed, ln_out_w, ln_out_b, out);
}

// round 10
// speedup vs baseline: 5.0952x; 1.0086x over previous
#include <cuda_runtime.h>
#include <cuda_bf16.h>
#include <cstdint>

// Problem constants
#define BB 8
#define LL 2048
#define DD 512
#define II 256
#define SS 8
#define DTR 32
#define ROWS (BB*LL)          // 16384
#define UCOLS 1536
#define RPER 16               // rows per k_prep block

// ---------------- scratch (static device globals; no runtime alloc) -------
__device__ float  g_h    [ROWS * 128];       // pos hidden (tf32-rounded)
__device__ float  g_pos  [ROWS * DD];        // pos MLP output
__device__ float  g_ubig [ROWS * UCOLS];     // [y_f, zb_f, y_b, zb_b, si] (tf32)
__device__ float  g_xzc  [ROWS * 1024];      // fused in-proj output (both dirs)
__device__ float2 g_dx   [2 * ROWS * II];    // (delta, xb) pairs
__device__ float2 g_bc   [2 * ROWS * SS];    // (bt, ct) pairs
__device__ float  g_mixed[ROWS * DD];
__device__ float  g_owT  [2 * DD * DD];      // transposed scan_out_w
__device__ float  g_wbig [DD * UCOLS];       // folded mix weight (tf32)
__device__ float  g_inwr [2 * DD * DD];      // tf32-rounded in_w
__device__ float  g_pw2r [DD * 128];         // tf32-rounded pos_w2

// ---------------- tf32 helpers ---------------------------------------------
__device__ __forceinline__ float tf32r(float f) {
    uint32_t r;
    asm("cvt.rna.tf32.f32 %0, %1;" : "=r"(r) : "f"(f));
    return __uint_as_float(r);
}

#define MMA_TF32(d, a, b) \
    asm volatile("mma.sync.aligned.m16n8k8.row.col.f32.tf32.tf32.f32 " \
        "{%0,%1,%2,%3}, {%4,%5,%6,%7}, {%8,%9}, {%0,%1,%2,%3};" \
        : "+f"(d[0]), "+f"(d[1]), "+f"(d[2]), "+f"(d[3]) \
        : "r"(a[0]), "r"(a[1]), "r"(a[2]), "r"(a[3]), "r"(b[0]), "r"(b[1]))

__device__ __forceinline__ void cp16(uint32_t dst, const float* src) {
    asm volatile("cp.async.cg.shared.global [%0], [%1], 16;"
                 :: "r"(dst), "l"(src));
}

// swizzled element offset within a 128x16 stage tile (element units)
__device__ __forceinline__ int dstoff(int r, int g) {
    return r * 16 + ((g ^ ((r >> 1) & 3)) << 2);
}

// ---------------- tf32 GEMM (cp.async, pre-rounded inputs) -----------------
// C[m,n] = sum_k A[m,k]*W[n,k].  BM=BN=128, BK=16, 4-stage pipeline.
// Inputs MUST be tf32-rounded already (raw-byte staging, no cvt).
__global__ __launch_bounds__(256, 2) void gemm_tf32(
    const float* __restrict__ A, int lda,
    const float* __restrict__ W, int ldw,
    float* __restrict__ C, int ldc, int K)
{
    extern __shared__ uint32_t sm[];   // 4 stages x (2048 A + 2048 W) u32
    const int bm = blockIdx.y * 128;
    const int bn = blockIdx.x * 128;
    const int tid = threadIdx.x;
    const int lane = tid & 31, wid = tid >> 5;
    const int wm = (wid & 1) * 64, wn = (wid >> 1) * 32;
    const int gr = lane >> 2, gc = lane & 3;
    const int sw = (gr >> 1) & 3;      // per-lane swizzle constant
    const int aG0 = (0 ^ sw) * 4, aG1 = (1 ^ sw) * 4;
    const int aG2 = (2 ^ sw) * 4, aG3 = (3 ^ sw) * 4;

    const int r0s = tid >> 2;          // staging row (u=0)
    const int gs  = tid & 3;           // staging 16B group
    uint32_t sb = (uint32_t)__cvta_generic_to_shared(sm);
    const int nk = K >> 4;

    float acc[4][4][4];
    #pragma unroll
    for (int mf = 0; mf < 4; mf++)
        #pragma unroll
        for (int nf = 0; nf < 4; nf++)
            #pragma unroll
            for (int e = 0; e < 4; e++) acc[mf][nf][e] = 0.f;

    // prologue: stages 0..2
    #pragma unroll
    for (int st = 0; st < 3; st++) {
        int k0 = st << 4;
        #pragma unroll
        for (int u = 0; u < 2; u++) {
            int r = r0s + u * 64;
            cp16(sb + (uint32_t)(st * 4096 + dstoff(r, gs)) * 4,
                 &A[(size_t)(bm + r) * lda + k0 + gs * 4]);
            cp16(sb + (uint32_t)(st * 4096 + 2048 + dstoff(r, gs)) * 4,
                 &W[(size_t)(bn + r) * ldw + k0 + gs * 4]);
        }
        asm volatile("cp.async.commit_group;");
    }

    for (int kt = 0; kt < nk; kt++) {
        asm volatile("cp.async.wait_group 2;");
        __syncthreads();
        if (kt + 3 < nk) {
            int st = kt + 3, slot = st & 3, k0 = st << 4;
            #pragma unroll
            for (int u = 0; u < 2; u++) {
                int r = r0s + u * 64;
                cp16(sb + (uint32_t)(slot * 4096 + dstoff(r, gs)) * 4,
                     &A[(size_t)(bm + r) * lda + k0 + gs * 4]);
                cp16(sb + (uint32_t)(slot * 4096 + 2048 + dstoff(r, gs)) * 4,
                     &W[(size_t)(bn + r) * ldw + k0 + gs * 4]);
            }
        }
        asm volatile("cp.async.commit_group;");

        const uint32_t* Asl = sm + (kt & 3) * 4096;
        const uint32_t* Wsl = Asl + 2048;
        #pragma unroll
        for (int ks = 0; ks < 2; ks++) {
            const int gA = ks ? aG2 : aG0;
            const int gB = ks ? aG3 : aG1;
            uint32_t af[4][4];
            #pragma unroll
            for (int mf = 0; mf < 4; mf++) {
                int rb = (wm + mf * 16 + gr) * 16 + gc;
                af[mf][0] = Asl[rb + gA];
                af[mf][1] = Asl[rb + 128 + gA];   // +8 rows
                af[mf][2] = Asl[rb + gB];
                af[mf][3] = Asl[rb + 128 + gB];
            }
            uint32_t bf[4][2];
            #pragma unroll
            for (int nf = 0; nf < 4; nf++) {
                int rb = (wn + nf * 8 + gr) * 16 + gc;
                bf[nf][0] = Wsl[rb + gA];
                bf[nf][1] = Wsl[rb + gB];
            }
            #pragma unroll
            for (int mf = 0; mf < 4; mf++)
                #pragma unroll
                for (int nf = 0; nf < 4; nf++)
                    MMA_TF32(acc[mf][nf], af[mf], bf[nf]);
        }
    }

    #pragma unroll
    for (int mf = 0; mf < 4; mf++) {
        #pragma unroll
        for (int nf = 0; nf < 4; nf++) {
            int r0 = bm + wm + mf * 16 + gr;
            int cc = bn + wn + nf * 8 + gc * 2;
            float2 v01 = make_float2(acc[mf][nf][0], acc[mf][nf][1]);
            float2 v23 = make_float2(acc[mf][nf][2], acc[mf][nf][3]);
            *reinterpret_cast<float2*>(&C[(size_t)r0 * ldc + cc]) = v01;
            *reinterpret_cast<float2*>(&C[(size_t)(r0 + 8) * ldc + cc]) = v23;
        }
    }
}

// ---------------- fp32 SGEMM (exact weight fold; tf32-rounds output) -------
__global__ __launch_bounds__(256) void sgemm_tn(
    const float* __restrict__ A, int lda,
    const float* __restrict__ W, int ldw,
    float* __restrict__ C, int ldc, int K)
{
    __shared__ float As[16][128];
    __shared__ float Ws[16][64];
    const int bm = blockIdx.y * 128;
    const int bn = blockIdx.x * 64;
    const int tid = threadIdx.x;
    const int tx = tid & 15;
    const int ty = tid >> 4;
    float acc[8][4];
    #pragma unroll
    for (int m = 0; m < 8; m++)
        #pragma unroll
        for (int n = 0; n < 4; n++) acc[m][n] = 0.f;

    for (int k0 = 0; k0 < K; k0 += 16) {
        #pragma unroll
        for (int u = 0; u < 2; u++) {
            int f = tid + u * 256;
            int row = f >> 2;
            int kk = (f & 3) * 4;
            float4 v = *reinterpret_cast<const float4*>(
                &A[(size_t)(bm + row) * lda + k0 + kk]);
            As[kk + 0][row] = v.x; As[kk + 1][row] = v.y;
            As[kk + 2][row] = v.z; As[kk + 3][row] = v.w;
        }
        {
            int row = tid >> 2;
            int kk = (tid & 3) * 4;
            float4 v = *reinterpret_cast<const float4*>(
                &W[(size_t)(bn + row) * ldw + k0 + kk]);
            Ws[kk + 0][row] = v.x; Ws[kk + 1][row] = v.y;
            Ws[kk + 2][row] = v.z; Ws[kk + 3][row] = v.w;
        }
        __syncthreads();
        #pragma unroll
        for (int kk = 0; kk < 16; kk++) {
            float af[8], wf[4];
            #pragma unroll
            for (int m = 0; m < 8; m++) af[m] = As[kk][ty * 8 + m];
            #pragma unroll
            for (int n = 0; n < 4; n++) wf[n] = Ws[kk][tx * 4 + n];
            #pragma unroll
            for (int m = 0; m < 8; m++)
                #pragma unroll
                for (int n = 0; n < 4; n++)
                    acc[m][n] = fmaf(af[m], wf[n], acc[m][n]);
        }
        __syncthreads();
    }
    #pragma unroll
    for (int m = 0; m < 8; m++) {
        float4 v = make_float4(tf32r(acc[m][0]), tf32r(acc[m][1]),
                               tf32r(acc[m][2]), tf32r(acc[m][3]));
        *reinterpret_cast<float4*>(
            &C[(size_t)(bm + ty * 8 + m) * ldc + bn + tx * 4]) = v;
    }
}

// ---------------- transpose 512x512 (per dir) ------------------------------
__global__ void k_transpose(const float* __restrict__ src, float* __restrict__ dst)
{
    __shared__ float tile[32][33];
    int d = blockIdx.z;
    src += (size_t)d * DD * DD;
    dst += (size_t)d * DD * DD;
    int x = blockIdx.x * 32 + threadIdx.x;
    int y = blockIdx.y * 32 + threadIdx.y;
    tile[threadIdx.y][threadIdx.x] = src[(size_t)y * DD + x];
    __syncthreads();
    x = blockIdx.y * 32 + threadIdx.x;
    y = blockIdx.x * 32 + threadIdx.y;
    dst[(size_t)y * DD + x] = tile[threadIdx.x][threadIdx.y];
}

// copy mix_w[:,1024:1536] into g_wbig[:,1024:1536], tf32-rounded
__global__ void k_copytail(const float* __restrict__ mixw, float* __restrict__ wbig)
{
    int idx = blockIdx.x * 256 + threadIdx.x;
    int n = idx >> 9, j = idx & 511;
    wbig[(size_t)n * UCOLS + 1024 + j] = tf32r(mixw[(size_t)n * UCOLS + 1024 + j]);
}

// tf32 round-copy
__global__ void k_round(const float* __restrict__ s, float* __restrict__ d, int n)
{
    int i = blockIdx.x * 256 + threadIdx.x;
    if (i < n) d[i] = tf32r(s[i]);
}

// ---------------- position MLP layer 1 (6 -> 128, exact GELU) --------------
__global__ void k_pos_h(const float* __restrict__ position,
                        const float* __restrict__ pw1,
                        const float* __restrict__ pb1,
                        float* __restrict__ h)
{
    int r = blockIdx.x, j = threadIdx.x;
    __shared__ float p[6];
    if (j < 6) p[j] = position[(size_t)r * 6 + j];
    __syncthreads();
    float acc = pb1[j];
    #pragma unroll
    for (int c = 0; c < 6; c++) acc = fmaf(pw1[j * 6 + c], p[c], acc);
    float g = 0.5f * acc * (1.f + erff(acc * 0.70710678118654752f));
    h[(size_t)r * 128 + j] = tf32r(g);
}

// ---------------- block reduce helper (256 threads) ------------------------
__device__ __forceinline__ float block_sum256(float v, float* sw, int t)
{
    #pragma unroll
    for (int o = 16; o > 0; o >>= 1) v += __shfl_xor_sync(0xffffffffu, v, o);
    if ((t & 31) == 0) sw[t >> 5] = v;
    __syncthreads();
    float r = sw[t & 7];
    #pragma unroll
    for (int o = 4; o > 0; o >>= 1) r += __shfl_xor_sync(0xffffffffu, r, o);
    return r;
}

// ---------------- input LN + pos add -> ubig si columns (tf32) -------------
__global__ void k_ln_in(const float* __restrict__ x,
                        const float* __restrict__ pos2,
                        const float* __restrict__ lnw, const float* __restrict__ lnb,
                        const float* __restrict__ pb2,
                        float* __restrict__ ubig)
{
    int r = blockIdx.x, t = threadIdx.x;
    const float* xr = x + (size_t)r * DD;
    float v0 = xr[t], v1 = xr[t + 256];
    __shared__ float sw[8];
    float total = block_sum256(v0 + v1, sw, t);
    float m = total * (1.f / 512.f);
    __syncthreads();
    float d0 = v0 - m, d1 = v1 - m;
    float vsum = block_sum256(d0 * d0 + d1 * d1, sw, t);
    float rs = rsqrtf(vsum * (1.f / 512.f) + 1e-6f);
    const float* pr = pos2 + (size_t)r * DD;
    float* u = ubig + (size_t)r * UCOLS + 1024;
    u[t]       = tf32r(d0 * rs * lnw[t]       + lnb[t]       + pr[t]       + pb2[t]);
    u[t + 256] = tf32r(d1 * rs * lnw[t + 256] + lnb[t + 256] + pr[t + 256] + pb2[t + 256]);
}

// ---------------- conv+silu + proj + delta ("prep"), blocked over rows -----
__global__ __launch_bounds__(256) void k_prep(
    const float* __restrict__ xzc,
    const float* __restrict__ cxw, const float* __restrict__ czw,
    const float* __restrict__ xpw,
    const float* __restrict__ dtw, const float* __restrict__ dtb,
    float2* __restrict__ dx, float2* __restrict__ bc,
    float* __restrict__ ubig)
{
    const int t = threadIdx.x;
    const int d = blockIdx.y;
    const int r0 = blockIdx.x * RPER;

    extern __shared__ float smf[];
    float* sxpw  = smf;                    // 48*256
    float* sdt   = smf + 12288;            // 256*33
    float* sxb   = smf + 12288 + 8448;     // 256
    float* sproj = sxb + 256;              // 48

    {
        const float4* xg = reinterpret_cast<const float4*>(xpw + (size_t)d * 48 * II);
        #pragma unroll
        for (int u = 0; u < 12; u++)
            reinterpret_cast<float4*>(sxpw)[t + u * 256] = xg[t + u * 256];
    }
    {
        const float4* dtg = reinterpret_cast<const float4*>(dtw + (size_t)d * II * DTR);
        #pragma unroll
        for (int u = 0; u < 8; u++) {
            int f = t + u * 256;
            float4 v = dtg[f];
            int tr = f >> 3, kc = (f & 7) * 4;
            sdt[tr * 33 + kc + 0] = v.x;
            sdt[tr * 33 + kc + 1] = v.y;
            sdt[tr * 33 + kc + 2] = v.z;
            sdt[tr * 33 + kc + 3] = v.w;
        }
    }

    const float* cwp = cxw + (size_t)(d * II + t) * 3;
    const float* zwp = czw + (size_t)(d * II + t) * 3;
    float cw0 = cwp[0], cw1 = cwp[1], cw2 = cwp[2];
    float zw0 = zwp[0], zw1 = zwp[1], zw2 = zwp[2];
    float bias = dtb[d * II + t];
    const int warp = t >> 5, lane = t & 31;
    __syncthreads();

    for (int rr = 0; rr < RPER; rr++) {
        int r = r0 + rr;
        int l = r & (LL - 1);
        size_t row = (size_t)r * 1024 + d * 512;
        float x0 = xzc[row + t];
        float z0 = xzc[row + 256 + t];
        float xm = 0.f, xp = 0.f, zm = 0.f, zp = 0.f;
        if (l > 0)      { xm = xzc[row - 1024 + t]; zm = xzc[row - 1024 + 256 + t]; }
        if (l < LL - 1) { xp = xzc[row + 1024 + t]; zp = xzc[row + 1024 + 256 + t]; }
        float xc, zc;
        if (d == 0) {
            xc = cw0 * xm + cw1 * x0 + cw2 * xp;
            zc = zw0 * zm + zw1 * z0 + zw2 * zp;
        } else {
            xc = cw0 * xp + cw1 * x0 + cw2 * xm;
            zc = zw0 * zp + zw1 * z0 + zw2 * zm;
        }
        float xbv = xc / (1.f + __expf(-xc));
        float zbv = zc / (1.f + __expf(-zc));
        sxb[t] = xbv;
        ubig[(size_t)r * UCOLS + (d ? 768 : 256) + t] = tf32r(zbv);
        __syncthreads();

        #pragma unroll
        for (int jj = 0; jj < 6; jj++) {
            int j = warp * 6 + jj;
            const float* wr = sxpw + j * 256;
            float p = 0.f;
            #pragma unroll
            for (int kk = 0; kk < 8; kk++)
                p = fmaf(sxb[lane + kk * 32], wr[lane + kk * 32], p);
            #pragma unroll
            for (int o = 16; o > 0; o >>= 1) p += __shfl_xor_sync(0xffffffffu, p, o);
            if (lane == 0) sproj[j] = p;
        }
        __syncthreads();

        if (t < 8) {
            bc[(size_t)(d * ROWS + r) * SS + t] =
                make_float2(tanhf(sproj[32 + t]), tanhf(sproj[40 + t]));
        }
        float acc = bias;
        const float* sr = &sdt[t * 33];
        #pragma unroll
        for (int k = 0; k < DTR; k++) acc = fmaf(sproj[k], sr[k], acc);
        float sp = (acc > 20.f) ? acc : log1pf(expf(acc));
        sp = fminf(fmaxf(sp, 1e-4f), 1.0f);
        dx[(size_t)(d * ROWS + r) * II + t] = make_float2(sp, xbv);
    }
}

// ---------------- sequential selective scan (batched prefetch) -------------
__global__ __launch_bounds__(256) void k_scan(
    const float2* __restrict__ dx, const float2* __restrict__ bc,
    const float* __restrict__ Alog, const float* __restrict__ Dp,
    float* __restrict__ ubig)
{
    int tid = blockIdx.x * 256 + threadIdx.x;
    int s = tid & 7;
    int chain = tid >> 3;
    int i = chain & (II - 1);
    int b = (chain >> 8) & (BB - 1);
    int d = chain >> 11;

    float a = log1pf(expf(Alog[(d * II + i) * SS + s])) + 1e-4f;
    float dp = Dp[d * II + i];

    int l0  = d ? (LL - 1) : 0;
    int sDX = d ? -II : II;
    int sBC = d ? -SS : SS;
    int sU  = d ? -UCOLS : UCOLS;
    int oDX = (d * ROWS + b * LL + l0) * II + i;
    int oBC = (d * ROWS + b * LL + l0) * SS + s;
    int oU  = b * LL * UCOLS + (d ? 512 : 0) + i + l0 * UCOLS;

    float state = 0.f;
    float2 cd[8], cb[8];
    #pragma unroll
    for (int u = 0; u < 8; u++) {
        cd[u] = dx[oDX + u * sDX];
        cb[u] = bc[oBC + u * sBC];
    }
    for (int n0 = 0; n0 < LL; n0 += 8) {
        float2 nd[8], nb[8];
        bool more = (n0 + 8 < LL);
        if (more) {
            int p1 = oDX + 8 * sDX;
            int p2 = oBC + 8 * sBC;
            #pragma unroll
            for (int u = 0; u < 8; u++) {
                nd[u] = dx[p1 + u * sDX];
                nb[u] = bc[p2 + u * sBC];
            }
        }
        #pragma unroll
        for (int u = 0; u < 8; u++) {
            float dec = __expf(-cd[u].x * a);
            dec = fminf(fmaxf(dec, 1e-4f), 1.0f);
            state = fmaf(dec, state, (1.f - dec) * (cb[u].x * cd[u].y));
            float part = state * cb[u].y;
            part += __shfl_xor_sync(0xffffffffu, part, 1);
            part += __shfl_xor_sync(0xffffffffu, part, 2);
            part += __shfl_xor_sync(0xffffffffu, part, 4);
            if (s == 0) ubig[oU + u * sU] = tf32r(part + dp * cd[u].y);
        }
        if (more) {
            #pragma unroll
            for (int u = 0; u < 8; u++) { cd[u] = nd[u]; cb[u] = nb[u]; }
        }
        oDX += 8 * sDX; oBC += 8 * sBC; oU += 8 * sU;
    }
}

// ---------------- output LN -------------------------------------------------
__global__ void k_ln_out(const float* __restrict__ mixed,
                         const float* __restrict__ w, const float* __restrict__ bias,
                         float* __restrict__ out)
{
    int r = blockIdx.x, t = threadIdx.x;
    const float* xr = mixed + (size_t)r * DD;
    float v0 = xr[t], v1 = xr[t + 256];
    __shared__ float sw[8];
    float total = block_sum256(v0 + v1, sw, t);
    float m = total * (1.f / 512.f);
    __syncthreads();
    float d0 = v0 - m, d1 = v1 - m;
    float vsum = block_sum256(d0 * d0 + d1 * d1, sw, t);
    float rs = rsqrtf(vsum * (1.f / 512.f) + 1e-6f);
    float* orow = out + (size_t)r * DD;
    orow[t]       = d0 * rs * w[t]       + bias[t];
    orow[t + 256] = d1 * rs * w[t + 256] + bias[t + 256];
}

// ---------------- host launch ----------------------------------------------
extern "C" void kernel_launch(void* const* d_in, const int* in_sizes, int n_in,
                              void* d_out, int out_size)
{
    const float* x        = (const float*)d_in[0];
    const float* position = (const float*)d_in[1];
    const float* ln_in_w  = (const float*)d_in[2];
    const float* ln_in_b  = (const float*)d_in[3];
    const float* pos_w1   = (const float*)d_in[4];
    const float* pos_b1   = (const float*)d_in[5];
    const float* pos_w2   = (const float*)d_in[6];
    const float* pos_b2   = (const float*)d_in[7];
    const float* in_w     = (const float*)d_in[8];
    const float* cx_w     = (const float*)d_in[9];
    const float* cz_w     = (const float*)d_in[10];
    const float* xp_w     = (const float*)d_in[11];
    const float* dt_w     = (const float*)d_in[12];
    const float* dt_b     = (const float*)d_in[13];
    const float* Alog     = (const float*)d_in[14];
    const float* Dp       = (const float*)d_in[15];
    const float* out_w    = (const float*)d_in[16];
    const float* mix_w    = (const float*)d_in[17];
    const float* ln_out_w = (const float*)d_in[18];
    const float* ln_out_b = (const float*)d_in[19];
    float* out = (float*)d_out;

    float  *p_h, *p_pos, *p_ubig, *p_xzc, *p_mixed, *p_owT, *p_wbig,
           *p_inwr, *p_pw2r;
    float2 *p_dx, *p_bc;
    cudaGetSymbolAddress((void**)&p_h,     g_h);
    cudaGetSymbolAddress((void**)&p_pos,   g_pos);
    cudaGetSymbolAddress((void**)&p_ubig,  g_ubig);
    cudaGetSymbolAddress((void**)&p_xzc,   g_xzc);
    cudaGetSymbolAddress((void**)&p_dx,    g_dx);
    cudaGetSymbolAddress((void**)&p_bc,    g_bc);
    cudaGetSymbolAddress((void**)&p_mixed, g_mixed);
    cudaGetSymbolAddress((void**)&p_owT,   g_owT);
    cudaGetSymbolAddress((void**)&p_wbig,  g_wbig);
    cudaGetSymbolAddress((void**)&p_inwr,  g_inwr);
    cudaGetSymbolAddress((void**)&p_pw2r,  g_pw2r);

    const int prep_smem = (12288 + 8448 + 256 + 48) * 4;
    cudaFuncSetAttribute(k_prep, cudaFuncAttributeMaxDynamicSharedMemorySize,
                         prep_smem);
    const int gemm_smem = 4 * 4096 * 4;   // 64 KB
    cudaFuncSetAttribute(gemm_tf32, cudaFuncAttributeMaxDynamicSharedMemorySize,
                         gemm_smem);

    // 0) tf32 round-copies of raw weights used by tensor GEMMs
    k_round<<<2048, 256>>>(in_w, p_inwr, 2 * DD * DD);
    k_round<<<256, 256>>>(pos_w2, p_pw2r, DD * 128);

    // 1) position MLP
    k_pos_h<<<ROWS, 128>>>(position, pos_w1, pos_b1, p_h);
    gemm_tf32<<<dim3(4, 128), 256, gemm_smem>>>(p_h, 128, p_pw2r, 128,
                                                p_pos, DD, 128);

    // 2) LN(x) + pos -> ubig si columns (tf32-rounded)
    k_ln_in<<<ROWS, 256>>>(x, p_pos, ln_in_w, ln_in_b, pos_b2, p_ubig);

    // 3) fused in-proj GEMM (both dirs, N=1024), then blocked prep
    gemm_tf32<<<dim3(8, 128), 256, gemm_smem>>>(p_ubig + 1024, UCOLS,
                                                p_inwr, DD, p_xzc, 1024, DD);
    k_prep<<<dim3(ROWS / RPER, 2), 256, prep_smem>>>(
        p_xzc, cx_w, cz_w, xp_w, dt_w, dt_b, p_dx, p_bc, p_ubig);

    // 4) both scans
    k_scan<<<128, 256>>>(p_dx, p_bc, Alog, Dp, p_ubig);

    // 5) fold out_w into mix_w (exact fp32 accumulate, tf32-rounded output)
    k_transpose<<<dim3(16, 16, 2), dim3(32, 32)>>>(out_w, p_owT);
    sgemm_tn<<<dim3(8, 4), 256>>>(mix_w,        UCOLS, p_owT,            DD,
                                  p_wbig,       UCOLS, DD);
    sgemm_tn<<<dim3(8, 4), 256>>>(mix_w + 512,  UCOLS, p_owT + DD * DD,  DD,
                                  p_wbig + 512, UCOLS, DD);
    k_copytail<<<1024, 256>>>(mix_w, p_wbig);

    // 6) fused out-proj + mix GEMM (tf32, K=1536)
    gemm_tf32<<<dim3(4, 128), 256, gemm_smem>>>(p_ubig, UCOLS, p_wbig, UCOLS,
                                                p_mixed, DD, UCOLS);

    // 7) output LN
    k_ln_out<<<ROWS, 256>>>(p_mixed, ln_out_w, ln_out_b, out);
}

// round 15
// speedup vs baseline: 5.5326x; 1.0858x over previous
#include <cuda_runtime.h>
#include <cuda_bf16.h>
#include <cstdint>

// Problem constants
#define BB 8
#define LL 2048
#define DD 512
#define II 256
#define SS 8
#define DTR 32
#define ROWS (BB*LL)          // 16384
#define UCOLS 1536
#define RPER 16               // rows per k_prep block

// ---------------- scratch (static device globals; no runtime alloc) -------
__device__ float  g_h    [ROWS * 128];       // pos hidden (tf32-rounded)
__device__ float  g_pos  [ROWS * DD];        // pos MLP output
__device__ float  g_ubig [ROWS * UCOLS];     // [y_f, zb_f, y_b, zb_b, si] (tf32)
__device__ float  g_xzc  [ROWS * 1024];      // fused in-proj output (both dirs)
__device__ float2 g_dx   [2 * ROWS * II];    // (delta, xb) pairs
__device__ float2 g_bc   [2 * ROWS * SS];    // (bt, ct) pairs
__device__ float  g_mixed[ROWS * DD];
__device__ float  g_owT  [2 * DD * DD];      // transposed scan_out_w (tf32)
__device__ float  g_wbig [DD * UCOLS];       // folded mix weight (tf32)
__device__ float  g_inwr [2 * DD * DD];      // tf32-rounded in_w
__device__ float  g_pw2r [DD * 128];         // tf32-rounded pos_w2
__device__ float  g_mixwr[DD * UCOLS];       // tf32-rounded mix_w

// ---------------- tf32 helpers ---------------------------------------------
__device__ __forceinline__ float tf32r(float f) {
    uint32_t r;
    asm("cvt.rna.tf32.f32 %0, %1;" : "=r"(r) : "f"(f));
    return __uint_as_float(r);
}

#define MMA_TF32(d, a, b) \
    asm volatile("mma.sync.aligned.m16n8k8.row.col.f32.tf32.tf32.f32 " \
        "{%0,%1,%2,%3}, {%4,%5,%6,%7}, {%8,%9}, {%0,%1,%2,%3};" \
        : "+f"(d[0]), "+f"(d[1]), "+f"(d[2]), "+f"(d[3]) \
        : "r"(a[0]), "r"(a[1]), "r"(a[2]), "r"(a[3]), "r"(b[0]), "r"(b[1]))

__device__ __forceinline__ void cp16(uint32_t dst, const float* src) {
    asm volatile("cp.async.cg.shared.global [%0], [%1], 16;"
                 :: "r"(dst), "l"(src));
}

// swizzled element offset within a 128x16 stage tile (element units)
__device__ __forceinline__ int dstoff(int r, int g) {
    return r * 16 + ((g ^ ((r >> 1) & 3)) << 2);
}

// ---------------- tf32 GEMM (cp.async, pre-rounded inputs) -----------------
// C[m,n] = sum_k A[m,k]*W[n,k].  BM=BN=128, BK=16, 4-stage pipeline.
// Inputs MUST be tf32-rounded already (raw-byte staging, no cvt).
__global__ __launch_bounds__(256, 2) void gemm_tf32(
    const float* __restrict__ A, int lda,
    const float* __restrict__ W, int ldw,
    float* __restrict__ C, int ldc, int K)
{
    extern __shared__ uint32_t sm[];   // 4 stages x (2048 A + 2048 W) u32
    const int bm = blockIdx.y * 128;
    const int bn = blockIdx.x * 128;
    const int tid = threadIdx.x;
    const int lane = tid & 31, wid = tid >> 5;
    const int wm = (wid & 1) * 64, wn = (wid >> 1) * 32;
    const int gr = lane >> 2, gc = lane & 3;
    const int sw = (gr >> 1) & 3;      // per-lane swizzle constant
    const int aG0 = (0 ^ sw) * 4, aG1 = (1 ^ sw) * 4;
    const int aG2 = (2 ^ sw) * 4, aG3 = (3 ^ sw) * 4;

    const int r0s = tid >> 2;          // staging row (u=0)
    const int gs  = tid & 3;           // staging 16B group
    uint32_t sb = (uint32_t)__cvta_generic_to_shared(sm);
    const int nk = K >> 4;

    float acc[4][4][4];
    #pragma unroll
    for (int mf = 0; mf < 4; mf++)
        #pragma unroll
        for (int nf = 0; nf < 4; nf++)
            #pragma unroll
            for (int e = 0; e < 4; e++) acc[mf][nf][e] = 0.f;

    // prologue: stages 0..2
    #pragma unroll
    for (int st = 0; st < 3; st++) {
        int k0 = st << 4;
        #pragma unroll
        for (int u = 0; u < 2; u++) {
            int r = r0s + u * 64;
            cp16(sb + (uint32_t)(st * 4096 + dstoff(r, gs)) * 4,
                 &A[(size_t)(bm + r) * lda + k0 + gs * 4]);
            cp16(sb + (uint32_t)(st * 4096 + 2048 + dstoff(r, gs)) * 4,
                 &W[(size_t)(bn + r) * ldw + k0 + gs * 4]);
        }
        asm volatile("cp.async.commit_group;");
    }

    for (int kt = 0; kt < nk; kt++) {
        asm volatile("cp.async.wait_group 2;");
        __syncthreads();
        if (kt + 3 < nk) {
            int st = kt + 3, slot = st & 3, k0 = st << 4;
            #pragma unroll
            for (int u = 0; u < 2; u++) {
                int r = r0s + u * 64;
                cp16(sb + (uint32_t)(slot * 4096 + dstoff(r, gs)) * 4,
                     &A[(size_t)(bm + r) * lda + k0 + gs * 4]);
                cp16(sb + (uint32_t)(slot * 4096 + 2048 + dstoff(r, gs)) * 4,
                     &W[(size_t)(bn + r) * ldw + k0 + gs * 4]);
            }
        }
        asm volatile("cp.async.commit_group;");

        const uint32_t* Asl = sm + (kt & 3) * 4096;
        const uint32_t* Wsl = Asl + 2048;
        #pragma unroll
        for (int ks = 0; ks < 2; ks++) {
            const int gA = ks ? aG2 : aG0;
            const int gB = ks ? aG3 : aG1;
            uint32_t af[4][4];
            #pragma unroll
            for (int mf = 0; mf < 4; mf++) {
                int rb = (wm + mf * 16 + gr) * 16 + gc;
                af[mf][0] = Asl[rb + gA];
                af[mf][1] = Asl[rb + 128 + gA];   // +8 rows
                af[mf][2] = Asl[rb + gB];
                af[mf][3] = Asl[rb + 128 + gB];
            }
            uint32_t bf[4][2];
            #pragma unroll
            for (int nf = 0; nf < 4; nf++) {
                int rb = (wn + nf * 8 + gr) * 16 + gc;
                bf[nf][0] = Wsl[rb + gA];
                bf[nf][1] = Wsl[rb + gB];
            }
            #pragma unroll
            for (int mf = 0; mf < 4; mf++)
                #pragma unroll
                for (int nf = 0; nf < 4; nf++)
                    MMA_TF32(acc[mf][nf], af[mf], bf[nf]);
        }
    }

    #pragma unroll
    for (int mf = 0; mf < 4; mf++) {
        #pragma unroll
        for (int nf = 0; nf < 4; nf++) {
            int r0 = bm + wm + mf * 16 + gr;
            int cc = bn + wn + nf * 8 + gc * 2;
            float2 v01 = make_float2(acc[mf][nf][0], acc[mf][nf][1]);
            float2 v23 = make_float2(acc[mf][nf][2], acc[mf][nf][3]);
            *reinterpret_cast<float2*>(&C[(size_t)r0 * ldc + cc]) = v01;
            *reinterpret_cast<float2*>(&C[(size_t)(r0 + 8) * ldc + cc]) = v23;
        }
    }
}

// ---------------- transpose 512x512 (per dir), tf32-rounds output ----------
__global__ void k_transpose(const float* __restrict__ src, float* __restrict__ dst)
{
    __shared__ float tile[32][33];
    int d = blockIdx.z;
    src += (size_t)d * DD * DD;
    dst += (size_t)d * DD * DD;
    int x = blockIdx.x * 32 + threadIdx.x;
    int y = blockIdx.y * 32 + threadIdx.y;
    tile[threadIdx.y][threadIdx.x] = src[(size_t)y * DD + x];
    __syncthreads();
    x = blockIdx.y * 32 + threadIdx.x;
    y = blockIdx.x * 32 + threadIdx.y;
    dst[(size_t)y * DD + x] = tf32r(tile[threadIdx.x][threadIdx.y]);
}

// copy mix_w[:,1024:1536] into g_wbig[:,1024:1536], tf32-rounded
__global__ void k_copytail(const float* __restrict__ mixw, float* __restrict__ wbig)
{
    int idx = blockIdx.x * 256 + threadIdx.x;
    int n = idx >> 9, j = idx & 511;
    wbig[(size_t)n * UCOLS + 1024 + j] = tf32r(mixw[(size_t)n * UCOLS + 1024 + j]);
}

// tf32 round-copy
__global__ void k_round(const float* __restrict__ s, float* __restrict__ d, int n)
{
    int i = blockIdx.x * 256 + threadIdx.x;
    if (i < n) d[i] = tf32r(s[i]);
}

// ---------------- position MLP layer 1 (6 -> 128, exact GELU) --------------
__global__ void k_pos_h(const float* __restrict__ position,
                        const float* __restrict__ pw1,
                        const float* __restrict__ pb1,
                        float* __restrict__ h)
{
    int r = blockIdx.x, j = threadIdx.x;
    __shared__ float p[6];
    if (j < 6) p[j] = position[(size_t)r * 6 + j];
    __syncthreads();
    float acc = pb1[j];
    #pragma unroll
    for (int c = 0; c < 6; c++) acc = fmaf(pw1[j * 6 + c], p[c], acc);
    float g = 0.5f * acc * (1.f + erff(acc * 0.70710678118654752f));
    h[(size_t)r * 128 + j] = tf32r(g);
}

// ---------------- block reduce helper (256 threads) ------------------------
__device__ __forceinline__ float block_sum256(float v, float* sw, int t)
{
    #pragma unroll
    for (int o = 16; o > 0; o >>= 1) v += __shfl_xor_sync(0xffffffffu, v, o);
    if ((t & 31) == 0) sw[t >> 5] = v;
    __syncthreads();
    float r = sw[t & 7];
    #pragma unroll
    for (int o = 4; o > 0; o >>= 1) r += __shfl_xor_sync(0xffffffffu, r, o);
    return r;
}

// ---------------- input LN + pos add -> ubig si columns (tf32) -------------
__global__ void k_ln_in(const float* __restrict__ x,
                        const float* __restrict__ pos2,
                        const float* __restrict__ lnw, const float* __restrict__ lnb,
                        const float* __restrict__ pb2,
                        float* __restrict__ ubig)
{
    int r = blockIdx.x, t = threadIdx.x;
    const float* xr = x + (size_t)r * DD;
    float v0 = xr[t], v1 = xr[t + 256];
    __shared__ float sw[8];
    float total = block_sum256(v0 + v1, sw, t);
    float m = total * (1.f / 512.f);
    __syncthreads();
    float d0 = v0 - m, d1 = v1 - m;
    float vsum = block_sum256(d0 * d0 + d1 * d1, sw, t);
    float rs = rsqrtf(vsum * (1.f / 512.f) + 1e-6f);
    const float* pr = pos2 + (size_t)r * DD;
    float* u = ubig + (size_t)r * UCOLS + 1024;
    u[t]       = tf32r(d0 * rs * lnw[t]       + lnb[t]       + pr[t]       + pb2[t]);
    u[t + 256] = tf32r(d1 * rs * lnw[t + 256] + lnb[t + 256] + pr[t + 256] + pb2[t + 256]);
}

// ---------------- conv+silu + proj + delta ("prep"), 3-phase ---------------
// grid (ROWS/RPER, 2). Weights staged once; 3 barriers per block total.
__global__ __launch_bounds__(256) void k_prep(
    const float* __restrict__ xzc,
    const float* __restrict__ cxw, const float* __restrict__ czw,
    const float* __restrict__ xpw,
    const float* __restrict__ dtw, const float* __restrict__ dtb,
    float2* __restrict__ dx, float2* __restrict__ bc,
    float* __restrict__ ubig)
{
    const int t = threadIdx.x;
    const int d = blockIdx.y;
    const int r0 = blockIdx.x * RPER;

    extern __shared__ float smf[];
    float* sxpw  = smf;                    // 48*256   = 12288
    float* sdt   = smf + 12288;            // 256*33   = 8448
    float* sxb   = smf + 12288 + 8448;     // RPER*256 = 4096
    float* sproj = sxb + RPER * 256;       // RPER*48  = 768
                                           // total 25600 floats = 102400 B
    // stage xp_w[d] (48x256) coalesced
    {
        const float4* xg = reinterpret_cast<const float4*>(xpw + (size_t)d * 48 * II);
        #pragma unroll
        for (int u = 0; u < 12; u++)
            reinterpret_cast<float4*>(sxpw)[t + u * 256] = xg[t + u * 256];
    }
    // stage dt_w[d] (256x32) into padded rows
    {
        const float4* dtg = reinterpret_cast<const float4*>(dtw + (size_t)d * II * DTR);
        #pragma unroll
        for (int u = 0; u < 8; u++) {
            int f = t + u * 256;
            float4 v = dtg[f];
            int tr = f >> 3, kc = (f & 7) * 4;
            sdt[tr * 33 + kc + 0] = v.x;
            sdt[tr * 33 + kc + 1] = v.y;
            sdt[tr * 33 + kc + 2] = v.z;
            sdt[tr * 33 + kc + 3] = v.w;
        }
    }

    const float* cwp = cxw + (size_t)(d * II + t) * 3;
    const float* zwp = czw + (size_t)(d * II + t) * 3;
    float cw0 = cwp[0], cw1 = cwp[1], cw2 = cwp[2];
    float zw0 = zwp[0], zw1 = zwp[1], zw2 = zwp[2];
    float bias = dtb[d * II + t];
    const int warp = t >> 5, lane = t & 31;

    // phase 1: conv + SiLU for all RPER rows (no barriers inside)
    float xv[RPER];
    #pragma unroll 4
    for (int rr = 0; rr < RPER; rr++) {
        int r = r0 + rr;
        int l = r & (LL - 1);
        size_t row = (size_t)r * 1024 + d * 512;
        float x0 = xzc[row + t];
        float z0 = xzc[row + 256 + t];
        float xm = 0.f, xp = 0.f, zm = 0.f, zp = 0.f;
        if (l > 0)      { xm = xzc[row - 1024 + t]; zm = xzc[row - 1024 + 256 + t]; }
        if (l < LL - 1) { xp = xzc[row + 1024 + t]; zp = xzc[row + 1024 + 256 + t]; }
        float xc, zc;
        if (d == 0) {
            xc = cw0 * xm + cw1 * x0 + cw2 * xp;
            zc = zw0 * zm + zw1 * z0 + zw2 * zp;
        } else {
            xc = cw0 * xp + cw1 * x0 + cw2 * xm;
            zc = zw0 * zp + zw1 * z0 + zw2 * zm;
        }
        float xbv = xc / (1.f + __expf(-xc));
        float zbv = zc / (1.f + __expf(-zc));
        xv[rr] = xbv;
        sxb[rr * 256 + t] = xbv;
        ubig[(size_t)(r0 + rr) * UCOLS + (d ? 768 : 256) + t] = tf32r(zbv);
    }
    __syncthreads();   // staging + phase1 visible

    // phase 2: projections for all rows (each warp owns 6 j-outputs)
    #pragma unroll
    for (int jj = 0; jj < 6; jj++) {
        int j = warp * 6 + jj;
        const float* wr = sxpw + j * 256;
        float w0 = wr[lane],       w1 = wr[lane + 32],  w2 = wr[lane + 64],
              w3 = wr[lane + 96],  w4 = wr[lane + 128], w5 = wr[lane + 160],
              w6 = wr[lane + 192], w7 = wr[lane + 224];
        for (int rr = 0; rr < RPER; rr++) {
            const float* xb = sxb + rr * 256;
            float p = w0 * xb[lane];
            p = fmaf(w1, xb[lane + 32], p);
            p = fmaf(w2, xb[lane + 64], p);
            p = fmaf(w3, xb[lane + 96], p);
            p = fmaf(w4, xb[lane + 128], p);
            p = fmaf(w5, xb[lane + 160], p);
            p = fmaf(w6, xb[lane + 192], p);
            p = fmaf(w7, xb[lane + 224], p);
            #pragma unroll
            for (int o = 16; o > 0; o >>= 1) p += __shfl_xor_sync(0xffffffffu, p, o);
            if (lane == 0) sproj[rr * 48 + j] = p;
        }
    }
    __syncthreads();

    // phase 3: bt/ct (128 threads cover 16 rows x 8 s), then delta for all rows
    if (t < RPER * 8) {
        int rr = t >> 3, s = t & 7;
        bc[(size_t)(d * ROWS + r0 + rr) * SS + s] =
            make_float2(tanhf(sproj[rr * 48 + 32 + s]), tanhf(sproj[rr * 48 + 40 + s]));
    }
    const float* sr = &sdt[t * 33];
    #pragma unroll 2
    for (int rr = 0; rr < RPER; rr++) {
        const float* pj = sproj + rr * 48;
        float acc = bias;
        #pragma unroll
        for (int k = 0; k < DTR; k++) acc = fmaf(pj[k], sr[k], acc);
        float sp = (acc > 20.f) ? acc : log1pf(expf(acc));
        sp = fminf(fmaxf(sp, 1e-4f), 1.0f);
        dx[(size_t)(d * ROWS + r0 + rr) * II + t] = make_float2(sp, xv[rr]);
    }
}

// ---------------- sequential selective scan (batched prefetch) -------------
__global__ __launch_bounds__(256) void k_scan(
    const float2* __restrict__ dx, const float2* __restrict__ bc,
    const float* __restrict__ Alog, const float* __restrict__ Dp,
    float* __restrict__ ubig)
{
    int tid = blockIdx.x * 256 + threadIdx.x;
    int s = tid & 7;
    int chain = tid >> 3;
    int i = chain & (II - 1);
    int b = (chain >> 8) & (BB - 1);
    int d = chain >> 11;

    float a = log1pf(expf(Alog[(d * II + i) * SS + s])) + 1e-4f;
    float dp = Dp[d * II + i];

    int l0  = d ? (LL - 1) : 0;
    int sDX = d ? -II : II;
    int sBC = d ? -SS : SS;
    int sU  = d ? -UCOLS : UCOLS;
    int oDX = (d * ROWS + b * LL + l0) * II + i;
    int oBC = (d * ROWS + b * LL + l0) * SS + s;
    int oU  = b * LL * UCOLS + (d ? 512 : 0) + i + l0 * UCOLS;

    float state = 0.f;
    float2 cd[8], cb[8];
    #pragma unroll
    for (int u = 0; u < 8; u++) {
        cd[u] = dx[oDX + u * sDX];
        cb[u] = bc[oBC + u * sBC];
    }
    for (int n0 = 0; n0 < LL; n0 += 8) {
        float2 nd[8], nb[8];
        bool more = (n0 + 8 < LL);
        if (more) {
            int p1 = oDX + 8 * sDX;
            int p2 = oBC + 8 * sBC;
            #pragma unroll
            for (int u = 0; u < 8; u++) {
                nd[u] = dx[p1 + u * sDX];
                nb[u] = bc[p2 + u * sBC];
            }
        }
        #pragma unroll
        for (int u = 0; u < 8; u++) {
            float dec = __expf(-cd[u].x * a);
            dec = fminf(fmaxf(dec, 1e-4f), 1.0f);
            state = fmaf(dec, state, (1.f - dec) * (cb[u].x * cd[u].y));
            float part = state * cb[u].y;
            part += __shfl_xor_sync(0xffffffffu, part, 1);
            part += __shfl_xor_sync(0xffffffffu, part, 2);
            part += __shfl_xor_sync(0xffffffffu, part, 4);
            if (s == 0) ubig[oU + u * sU] = tf32r(part + dp * cd[u].y);
        }
        if (more) {
            #pragma unroll
            for (int u = 0; u < 8; u++) { cd[u] = nd[u]; cb[u] = nb[u]; }
        }
        oDX += 8 * sDX; oBC += 8 * sBC; oU += 8 * sU;
    }
}

// ---------------- output LN -------------------------------------------------
__global__ void k_ln_out(const float* __restrict__ mixed,
                         const float* __restrict__ w, const float* __restrict__ bias,
                         float* __restrict__ out)
{
    int r = blockIdx.x, t = threadIdx.x;
    const float* xr = mixed + (size_t)r * DD;
    float v0 = xr[t], v1 = xr[t + 256];
    __shared__ float sw[8];
    float total = block_sum256(v0 + v1, sw, t);
    float m = total * (1.f / 512.f);
    __syncthreads();
    float d0 = v0 - m, d1 = v1 - m;
    float vsum = block_sum256(d0 * d0 + d1 * d1, sw, t);
    float rs = rsqrtf(vsum * (1.f / 512.f) + 1e-6f);
    float* orow = out + (size_t)r * DD;
    orow[t]       = d0 * rs * w[t]       + bias[t];
    orow[t + 256] = d1 * rs * w[t + 256] + bias[t + 256];
}

// ---------------- host launch ----------------------------------------------
extern "C" void kernel_launch(void* const* d_in, const int* in_sizes, int n_in,
                              void* d_out, int out_size)
{
    const float* x        = (const float*)d_in[0];
    const float* position = (const float*)d_in[1];
    const float* ln_in_w  = (const float*)d_in[2];
    const float* ln_in_b  = (const float*)d_in[3];
    const float* pos_w1   = (const float*)d_in[4];
    const float* pos_b1   = (const float*)d_in[5];
    const float* pos_w2   = (const float*)d_in[6];
    const float* pos_b2   = (const float*)d_in[7];
    const float* in_w     = (const float*)d_in[8];
    const float* cx_w     = (const float*)d_in[9];
    const float* cz_w     = (const float*)d_in[10];
    const float* xp_w     = (const float*)d_in[11];
    const float* dt_w     = (const float*)d_in[12];
    const float* dt_b     = (const float*)d_in[13];
    const float* Alog     = (const float*)d_in[14];
    const float* Dp       = (const float*)d_in[15];
    const float* out_w    = (const float*)d_in[16];
    const float* mix_w    = (const float*)d_in[17];
    const float* ln_out_w = (const float*)d_in[18];
    const float* ln_out_b = (const float*)d_in[19];
    float* out = (float*)d_out;

    float  *p_h, *p_pos, *p_ubig, *p_xzc, *p_mixed, *p_owT, *p_wbig,
           *p_inwr, *p_pw2r, *p_mixwr;
    float2 *p_dx, *p_bc;
    cudaGetSymbolAddress((void**)&p_h,     g_h);
    cudaGetSymbolAddress((void**)&p_pos,   g_pos);
    cudaGetSymbolAddress((void**)&p_ubig,  g_ubig);
    cudaGetSymbolAddress((void**)&p_xzc,   g_xzc);
    cudaGetSymbolAddress((void**)&p_dx,    g_dx);
    cudaGetSymbolAddress((void**)&p_bc,    g_bc);
    cudaGetSymbolAddress((void**)&p_mixed, g_mixed);
    cudaGetSymbolAddress((void**)&p_owT,   g_owT);
    cudaGetSymbolAddress((void**)&p_wbig,  g_wbig);
    cudaGetSymbolAddress((void**)&p_inwr,  g_inwr);
    cudaGetSymbolAddress((void**)&p_pw2r,  g_pw2r);
    cudaGetSymbolAddress((void**)&p_mixwr, g_mixwr);

    const int prep_smem = (12288 + 8448 + RPER * 256 + RPER * 48) * 4; // 102400
    cudaFuncSetAttribute(k_prep, cudaFuncAttributeMaxDynamicSharedMemorySize,
                         prep_smem);
    const int gemm_smem = 4 * 4096 * 4;   // 64 KB
    cudaFuncSetAttribute(gemm_tf32, cudaFuncAttributeMaxDynamicSharedMemorySize,
                         gemm_smem);

    // 0) tf32 round-copies of raw weights used by tensor GEMMs
    k_round<<<2048, 256>>>(in_w, p_inwr, 2 * DD * DD);
    k_round<<<256, 256>>>(pos_w2, p_pw2r, DD * 128);

    // 1) position MLP
    k_pos_h<<<ROWS, 128>>>(position, pos_w1, pos_b1, p_h);
    gemm_tf32<<<dim3(4, 128), 256, gemm_smem>>>(p_h, 128, p_pw2r, 128,
                                                p_pos, DD, 128);

    // 2) LN(x) + pos -> ubig si columns (tf32-rounded)
    k_ln_in<<<ROWS, 256>>>(x, p_pos, ln_in_w, ln_in_b, pos_b2, p_ubig);

    // 3) fused in-proj GEMM (both dirs, N=1024), then 3-phase prep
    gemm_tf32<<<dim3(8, 128), 256, gemm_smem>>>(p_ubig + 1024, UCOLS,
                                                p_inwr, DD, p_xzc, 1024, DD);
    k_prep<<<dim3(ROWS / RPER, 2), 256, prep_smem>>>(
        p_xzc, cx_w, cz_w, xp_w, dt_w, dt_b, p_dx, p_bc, p_ubig);

    // 4) both scans
    k_scan<<<128, 256>>>(p_dx, p_bc, Alog, Dp, p_ubig);

    // 5) fold out_w into mix_w (tf32 tensor GEMMs)
    k_transpose<<<dim3(16, 16, 2), dim3(32, 32)>>>(out_w, p_owT);
    k_round<<<3072, 256>>>(mix_w, p_mixwr, DD * UCOLS);
    gemm_tf32<<<dim3(4, 4), 256, gemm_smem>>>(p_mixwr,       UCOLS, p_owT,
                                              DD, p_wbig,       UCOLS, DD);
    gemm_tf32<<<dim3(4, 4), 256, gemm_smem>>>(p_mixwr + 512, UCOLS, p_owT + DD * DD,
                                              DD, p_wbig + 512, UCOLS, DD);
    k_copytail<<<1024, 256>>>(mix_w, p_wbig);

    // 6) fused out-proj + mix GEMM (tf32, K=1536)
    gemm_tf32<<<dim3(4, 128), 256, gemm_smem>>>(p_ubig, UCOLS, p_wbig, UCOLS,
                                                p_mixed, DD, UCOLS);

    // 7) output LN
    k_ln_out<<<ROWS, 256>>>(p_mixed, ln_out_w, ln_out_b, out);
}

// round 16
// speedup vs baseline: 5.7612x; 1.0413x over previous
#include <cuda_runtime.h>
#include <cuda_bf16.h>
#include <cstdint>

// Problem constants
#define BB 8
#define LL 2048
#define DD 512
#define II 256
#define SS 8
#define DTR 32
#define ROWS (BB*LL)          // 16384
#define UCOLS 1536
#define RPER 16               // rows per k_prep block

// ---------------- scratch (static device globals; no runtime alloc) -------
__device__ float  g_h    [ROWS * 128];       // pos hidden (tf32-rounded)
__device__ float  g_pos  [ROWS * DD];        // pos MLP output
__device__ float  g_ubig [ROWS * UCOLS];     // [y_f, zb_f, y_b, zb_b, si] (tf32)
__device__ float  g_xzc  [ROWS * 1024];      // fused in-proj output (both dirs)
__device__ float2 g_dx   [2 * ROWS * II];    // (delta, xb) pairs
__device__ float2 g_bc   [2 * ROWS * SS];    // (bt, ct) pairs
__device__ float  g_mixed[ROWS * DD];
__device__ float  g_owT  [2 * DD * DD];      // transposed scan_out_w (tf32)
__device__ float  g_wbig [DD * UCOLS];       // folded mix weight (tf32)
__device__ float  g_inwr [2 * DD * DD];      // tf32-rounded in_w
__device__ float  g_pw2r [DD * 128];         // tf32-rounded pos_w2
__device__ float  g_mixwr[DD * UCOLS];       // tf32-rounded mix_w

// ---------------- tf32 helpers ---------------------------------------------
__device__ __forceinline__ float tf32r(float f) {
    uint32_t r;
    asm("cvt.rna.tf32.f32 %0, %1;" : "=r"(r) : "f"(f));
    return __uint_as_float(r);
}

#define MMA_TF32(d, a, b) \
    asm volatile("mma.sync.aligned.m16n8k8.row.col.f32.tf32.tf32.f32 " \
        "{%0,%1,%2,%3}, {%4,%5,%6,%7}, {%8,%9}, {%0,%1,%2,%3};" \
        : "+f"(d[0]), "+f"(d[1]), "+f"(d[2]), "+f"(d[3]) \
        : "r"(a[0]), "r"(a[1]), "r"(a[2]), "r"(a[3]), "r"(b[0]), "r"(b[1]))

__device__ __forceinline__ void cp16(uint32_t dst, const float* src) {
    asm volatile("cp.async.cg.shared.global [%0], [%1], 16;"
                 :: "r"(dst), "l"(src));
}

// swizzled element offset within a 128x16 stage tile (element units)
__device__ __forceinline__ int dstoff(int r, int g) {
    return r * 16 + ((g ^ ((r >> 1) & 3)) << 2);
}

// ---------------- tf32 GEMM (cp.async, pre-rounded inputs) -----------------
// C[m,n] = sum_k A[m,k]*W[n,k].  BM=BN=128, BK=16, 4-stage pipeline.
// Inputs MUST be tf32-rounded already (raw-byte staging, no cvt).
__global__ __launch_bounds__(256, 2) void gemm_tf32(
    const float* __restrict__ A, int lda,
    const float* __restrict__ W, int ldw,
    float* __restrict__ C, int ldc, int K)
{
    extern __shared__ uint32_t sm[];   // 4 stages x (2048 A + 2048 W) u32
    const int bm = blockIdx.y * 128;
    const int bn = blockIdx.x * 128;
    const int tid = threadIdx.x;
    const int lane = tid & 31, wid = tid >> 5;
    const int wm = (wid & 1) * 64, wn = (wid >> 1) * 32;
    const int gr = lane >> 2, gc = lane & 3;
    const int sw = (gr >> 1) & 3;      // per-lane swizzle constant
    const int aG0 = (0 ^ sw) * 4, aG1 = (1 ^ sw) * 4;
    const int aG2 = (2 ^ sw) * 4, aG3 = (3 ^ sw) * 4;

    const int r0s = tid >> 2;          // staging row (u=0)
    const int gs  = tid & 3;           // staging 16B group
    uint32_t sb = (uint32_t)__cvta_generic_to_shared(sm);
    const int nk = K >> 4;

    float acc[4][4][4];
    #pragma unroll
    for (int mf = 0; mf < 4; mf++)
        #pragma unroll
        for (int nf = 0; nf < 4; nf++)
            #pragma unroll
            for (int e = 0; e < 4; e++) acc[mf][nf][e] = 0.f;

    // prologue: stages 0..2
    #pragma unroll
    for (int st = 0; st < 3; st++) {
        int k0 = st << 4;
        #pragma unroll
        for (int u = 0; u < 2; u++) {
            int r = r0s + u * 64;
            cp16(sb + (uint32_t)(st * 4096 + dstoff(r, gs)) * 4,
                 &A[(size_t)(bm + r) * lda + k0 + gs * 4]);
            cp16(sb + (uint32_t)(st * 4096 + 2048 + dstoff(r, gs)) * 4,
                 &W[(size_t)(bn + r) * ldw + k0 + gs * 4]);
        }
        asm volatile("cp.async.commit_group;");
    }

    for (int kt = 0; kt < nk; kt++) {
        asm volatile("cp.async.wait_group 2;");
        __syncthreads();
        if (kt + 3 < nk) {
            int st = kt + 3, slot = st & 3, k0 = st << 4;
            #pragma unroll
            for (int u = 0; u < 2; u++) {
                int r = r0s + u * 64;
                cp16(sb + (uint32_t)(slot * 4096 + dstoff(r, gs)) * 4,
                     &A[(size_t)(bm + r) * lda + k0 + gs * 4]);
                cp16(sb + (uint32_t)(slot * 4096 + 2048 + dstoff(r, gs)) * 4,
                     &W[(size_t)(bn + r) * ldw + k0 + gs * 4]);
            }
        }
        asm volatile("cp.async.commit_group;");

        const uint32_t* Asl = sm + (kt & 3) * 4096;
        const uint32_t* Wsl = Asl + 2048;
        #pragma unroll
        for (int ks = 0; ks < 2; ks++) {
            const int gA = ks ? aG2 : aG0;
            const int gB = ks ? aG3 : aG1;
            uint32_t af[4][4];
            #pragma unroll
            for (int mf = 0; mf < 4; mf++) {
                int rb = (wm + mf * 16 + gr) * 16 + gc;
                af[mf][0] = Asl[rb + gA];
                af[mf][1] = Asl[rb + 128 + gA];   // +8 rows
                af[mf][2] = Asl[rb + gB];
                af[mf][3] = Asl[rb + 128 + gB];
            }
            uint32_t bf[4][2];
            #pragma unroll
            for (int nf = 0; nf < 4; nf++) {
                int rb = (wn + nf * 8 + gr) * 16 + gc;
                bf[nf][0] = Wsl[rb + gA];
                bf[nf][1] = Wsl[rb + gB];
            }
            #pragma unroll
            for (int mf = 0; mf < 4; mf++)
                #pragma unroll
                for (int nf = 0; nf < 4; nf++)
                    MMA_TF32(acc[mf][nf], af[mf], bf[nf]);
        }
    }

    #pragma unroll
    for (int mf = 0; mf < 4; mf++) {
        #pragma unroll
        for (int nf = 0; nf < 4; nf++) {
            int r0 = bm + wm + mf * 16 + gr;
            int cc = bn + wn + nf * 8 + gc * 2;
            float2 v01 = make_float2(acc[mf][nf][0], acc[mf][nf][1]);
            float2 v23 = make_float2(acc[mf][nf][2], acc[mf][nf][3]);
            *reinterpret_cast<float2*>(&C[(size_t)r0 * ldc + cc]) = v01;
            *reinterpret_cast<float2*>(&C[(size_t)(r0 + 8) * ldc + cc]) = v23;
        }
    }
}

// ---------------- transpose 512x512 (per dir), tf32-rounds output ----------
__global__ void k_transpose(const float* __restrict__ src, float* __restrict__ dst)
{
    __shared__ float tile[32][33];
    int d = blockIdx.z;
    src += (size_t)d * DD * DD;
    dst += (size_t)d * DD * DD;
    int x = blockIdx.x * 32 + threadIdx.x;
    int y = blockIdx.y * 32 + threadIdx.y;
    tile[threadIdx.y][threadIdx.x] = src[(size_t)y * DD + x];
    __syncthreads();
    x = blockIdx.y * 32 + threadIdx.x;
    y = blockIdx.x * 32 + threadIdx.y;
    dst[(size_t)y * DD + x] = tf32r(tile[threadIdx.x][threadIdx.y]);
}

// copy mix_w[:,1024:1536] into g_wbig[:,1024:1536], tf32-rounded
__global__ void k_copytail(const float* __restrict__ mixw, float* __restrict__ wbig)
{
    int idx = blockIdx.x * 256 + threadIdx.x;
    int n = idx >> 9, j = idx & 511;
    wbig[(size_t)n * UCOLS + 1024 + j] = tf32r(mixw[(size_t)n * UCOLS + 1024 + j]);
}

// tf32 round-copy
__global__ void k_round(const float* __restrict__ s, float* __restrict__ d, int n)
{
    int i = blockIdx.x * 256 + threadIdx.x;
    if (i < n) d[i] = tf32r(s[i]);
}

// ---------------- position MLP layer 1 (6 -> 128, exact GELU) --------------
__global__ void k_pos_h(const float* __restrict__ position,
                        const float* __restrict__ pw1,
                        const float* __restrict__ pb1,
                        float* __restrict__ h)
{
    int r = blockIdx.x, j = threadIdx.x;
    __shared__ float p[6];
    if (j < 6) p[j] = position[(size_t)r * 6 + j];
    __syncthreads();
    float acc = pb1[j];
    #pragma unroll
    for (int c = 0; c < 6; c++) acc = fmaf(pw1[j * 6 + c], p[c], acc);
    float g = 0.5f * acc * (1.f + erff(acc * 0.70710678118654752f));
    h[(size_t)r * 128 + j] = tf32r(g);
}

// ---------------- block reduce helper (256 threads) ------------------------
__device__ __forceinline__ float block_sum256(float v, float* sw, int t)
{
    #pragma unroll
    for (int o = 16; o > 0; o >>= 1) v += __shfl_xor_sync(0xffffffffu, v, o);
    if ((t & 31) == 0) sw[t >> 5] = v;
    __syncthreads();
    float r = sw[t & 7];
    #pragma unroll
    for (int o = 4; o > 0; o >>= 1) r += __shfl_xor_sync(0xffffffffu, r, o);
    return r;
}

// ---------------- input LN + pos add -> ubig si columns (tf32) -------------
__global__ void k_ln_in(const float* __restrict__ x,
                        const float* __restrict__ pos2,
                        const float* __restrict__ lnw, const float* __restrict__ lnb,
                        const float* __restrict__ pb2,
                        float* __restrict__ ubig)
{
    int r = blockIdx.x, t = threadIdx.x;
    const float* xr = x + (size_t)r * DD;
    float v0 = xr[t], v1 = xr[t + 256];
    __shared__ float sw[8];
    float total = block_sum256(v0 + v1, sw, t);
    float m = total * (1.f / 512.f);
    __syncthreads();
    float d0 = v0 - m, d1 = v1 - m;
    float vsum = block_sum256(d0 * d0 + d1 * d1, sw, t);
    float rs = rsqrtf(vsum * (1.f / 512.f) + 1e-6f);
    const float* pr = pos2 + (size_t)r * DD;
    float* u = ubig + (size_t)r * UCOLS + 1024;
    u[t]       = tf32r(d0 * rs * lnw[t]       + lnb[t]       + pr[t]       + pb2[t]);
    u[t + 256] = tf32r(d1 * rs * lnw[t + 256] + lnb[t + 256] + pr[t + 256] + pb2[t + 256]);
}

// ---------------- conv+silu + proj + delta ("prep"), 3-phase ---------------
// grid (ROWS/RPER, 2). Weights staged once; 3 barriers per block total.
__global__ __launch_bounds__(256) void k_prep(
    const float* __restrict__ xzc,
    const float* __restrict__ cxw, const float* __restrict__ czw,
    const float* __restrict__ xpw,
    const float* __restrict__ dtw, const float* __restrict__ dtb,
    float2* __restrict__ dx, float2* __restrict__ bc,
    float* __restrict__ ubig)
{
    const int t = threadIdx.x;
    const int d = blockIdx.y;
    const int r0 = blockIdx.x * RPER;

    extern __shared__ float smf[];
    float* sxpw  = smf;                    // 48*256   = 12288
    float* sdt   = smf + 12288;            // 256*33   = 8448
    float* sxb   = smf + 12288 + 8448;     // RPER*256 = 4096
    float* sproj = sxb + RPER * 256;       // RPER*48  = 768
                                           // total 25600 floats = 102400 B
    // stage xp_w[d] (48x256) coalesced
    {
        const float4* xg = reinterpret_cast<const float4*>(xpw + (size_t)d * 48 * II);
        #pragma unroll
        for (int u = 0; u < 12; u++)
            reinterpret_cast<float4*>(sxpw)[t + u * 256] = xg[t + u * 256];
    }
    // stage dt_w[d] (256x32) into padded rows
    {
        const float4* dtg = reinterpret_cast<const float4*>(dtw + (size_t)d * II * DTR);
        #pragma unroll
        for (int u = 0; u < 8; u++) {
            int f = t + u * 256;
            float4 v = dtg[f];
            int tr = f >> 3, kc = (f & 7) * 4;
            sdt[tr * 33 + kc + 0] = v.x;
            sdt[tr * 33 + kc + 1] = v.y;
            sdt[tr * 33 + kc + 2] = v.z;
            sdt[tr * 33 + kc + 3] = v.w;
        }
    }

    const float* cwp = cxw + (size_t)(d * II + t) * 3;
    const float* zwp = czw + (size_t)(d * II + t) * 3;
    float cw0 = cwp[0], cw1 = cwp[1], cw2 = cwp[2];
    float zw0 = zwp[0], zw1 = zwp[1], zw2 = zwp[2];
    float bias = dtb[d * II + t];
    const int warp = t >> 5, lane = t & 31;

    // phase 1: conv + SiLU for all RPER rows (no barriers inside)
    float xv[RPER];
    #pragma unroll 4
    for (int rr = 0; rr < RPER; rr++) {
        int r = r0 + rr;
        int l = r & (LL - 1);
        size_t row = (size_t)r * 1024 + d * 512;
        float x0 = xzc[row + t];
        float z0 = xzc[row + 256 + t];
        float xm = 0.f, xp = 0.f, zm = 0.f, zp = 0.f;
        if (l > 0)      { xm = xzc[row - 1024 + t]; zm = xzc[row - 1024 + 256 + t]; }
        if (l < LL - 1) { xp = xzc[row + 1024 + t]; zp = xzc[row + 1024 + 256 + t]; }
        float xc, zc;
        if (d == 0) {
            xc = cw0 * xm + cw1 * x0 + cw2 * xp;
            zc = zw0 * zm + zw1 * z0 + zw2 * zp;
        } else {
            xc = cw0 * xp + cw1 * x0 + cw2 * xm;
            zc = zw0 * zp + zw1 * z0 + zw2 * zm;
        }
        float xbv = xc / (1.f + __expf(-xc));
        float zbv = zc / (1.f + __expf(-zc));
        xv[rr] = xbv;
        sxb[rr * 256 + t] = xbv;
        ubig[(size_t)(r0 + rr) * UCOLS + (d ? 768 : 256) + t] = tf32r(zbv);
    }
    __syncthreads();   // staging + phase1 visible

    // phase 2: projections for all rows (each warp owns 6 j-outputs)
    #pragma unroll
    for (int jj = 0; jj < 6; jj++) {
        int j = warp * 6 + jj;
        const float* wr = sxpw + j * 256;
        float w0 = wr[lane],       w1 = wr[lane + 32],  w2 = wr[lane + 64],
              w3 = wr[lane + 96],  w4 = wr[lane + 128], w5 = wr[lane + 160],
              w6 = wr[lane + 192], w7 = wr[lane + 224];
        for (int rr = 0; rr < RPER; rr++) {
            const float* xb = sxb + rr * 256;
            float p = w0 * xb[lane];
            p = fmaf(w1, xb[lane + 32], p);
            p = fmaf(w2, xb[lane + 64], p);
            p = fmaf(w3, xb[lane + 96], p);
            p = fmaf(w4, xb[lane + 128], p);
            p = fmaf(w5, xb[lane + 160], p);
            p = fmaf(w6, xb[lane + 192], p);
            p = fmaf(w7, xb[lane + 224], p);
            #pragma unroll
            for (int o = 16; o > 0; o >>= 1) p += __shfl_xor_sync(0xffffffffu, p, o);
            if (lane == 0) sproj[rr * 48 + j] = p;
        }
    }
    __syncthreads();

    // phase 3: bt/ct (128 threads cover 16 rows x 8 s), then delta for all rows
    if (t < RPER * 8) {
        int rr = t >> 3, s = t & 7;
        bc[(size_t)(d * ROWS + r0 + rr) * SS + s] =
            make_float2(tanhf(sproj[rr * 48 + 32 + s]), tanhf(sproj[rr * 48 + 40 + s]));
    }
    const float* sr = &sdt[t * 33];
    #pragma unroll 2
    for (int rr = 0; rr < RPER; rr++) {
        const float* pj = sproj + rr * 48;
        float acc = bias;
        #pragma unroll
        for (int k = 0; k < DTR; k++) acc = fmaf(pj[k], sr[k], acc);
        float sp = (acc > 20.f) ? acc : log1pf(expf(acc));
        sp = fminf(fmaxf(sp, 1e-4f), 1.0f);
        dx[(size_t)(d * ROWS + r0 + rr) * II + t] = make_float2(sp, xv[rr]);
    }
}

// ---------------- sequential selective scan (batched prefetch) -------------
__global__ __launch_bounds__(256) void k_scan(
    const float2* __restrict__ dx, const float2* __restrict__ bc,
    const float* __restrict__ Alog, const float* __restrict__ Dp,
    float* __restrict__ ubig)
{
    int tid = blockIdx.x * 256 + threadIdx.x;
    int s = tid & 7;
    int chain = tid >> 3;
    int i = chain & (II - 1);
    int b = (chain >> 8) & (BB - 1);
    int d = chain >> 11;

    float a = log1pf(expf(Alog[(d * II + i) * SS + s])) + 1e-4f;
    float dp = Dp[d * II + i];

    int l0  = d ? (LL - 1) : 0;
    int sDX = d ? -II : II;
    int sBC = d ? -SS : SS;
    int sU  = d ? -UCOLS : UCOLS;
    int oDX = (d * ROWS + b * LL + l0) * II + i;
    int oBC = (d * ROWS + b * LL + l0) * SS + s;
    int oU  = b * LL * UCOLS + (d ? 512 : 0) + i + l0 * UCOLS;

    float state = 0.f;
    float2 cd[8], cb[8];
    #pragma unroll
    for (int u = 0; u < 8; u++) {
        cd[u] = dx[oDX + u * sDX];
        cb[u] = bc[oBC + u * sBC];
    }
    for (int n0 = 0; n0 < LL; n0 += 8) {
        float2 nd[8], nb[8];
        bool more = (n0 + 8 < LL);
        if (more) {
            int p1 = oDX + 8 * sDX;
            int p2 = oBC + 8 * sBC;
            #pragma unroll
            for (int u = 0; u < 8; u++) {
                nd[u] = dx[p1 + u * sDX];
                nb[u] = bc[p2 + u * sBC];
            }
        }
        #pragma unroll
        for (int u = 0; u < 8; u++) {
            float dec = __expf(-cd[u].x * a);
            dec = fminf(fmaxf(dec, 1e-4f), 1.0f);
            state = fmaf(dec, state, (1.f - dec) * (cb[u].x * cd[u].y));
            float part = state * cb[u].y;
            part += __shfl_xor_sync(0xffffffffu, part, 1);
            part += __shfl_xor_sync(0xffffffffu, part, 2);
            part += __shfl_xor_sync(0xffffffffu, part, 4);
            if (s == 0) ubig[oU + u * sU] = tf32r(part + dp * cd[u].y);
        }
        if (more) {
            #pragma unroll
            for (int u = 0; u < 8; u++) { cd[u] = nd[u]; cb[u] = nb[u]; }
        }
        oDX += 8 * sDX; oBC += 8 * sBC; oU += 8 * sU;
    }
}

// ---------------- output LN -------------------------------------------------
__global__ void k_ln_out(const float* __restrict__ mixed,
                         const float* __restrict__ w, const float* __restrict__ bias,
                         float* __restrict__ out)
{
    int r = blockIdx.x, t = threadIdx.x;
    const float* xr = mixed + (size_t)r * DD;
    float v0 = xr[t], v1 = xr[t + 256];
    __shared__ float sw[8];
    float total = block_sum256(v0 + v1, sw, t);
    float m = total * (1.f / 512.f);
    __syncthreads();
    float d0 = v0 - m, d1 = v1 - m;
    float vsum = block_sum256(d0 * d0 + d1 * d1, sw, t);
    float rs = rsqrtf(vsum * (1.f / 512.f) + 1e-6f);
    float* orow = out + (size_t)r * DD;
    orow[t]       = d0 * rs * w[t]       + bias[t];
    orow[t + 256] = d1 * rs * w[t + 256] + bias[t + 256];
}

// ---------------- host launch ----------------------------------------------
extern "C" void kernel_launch(void* const* d_in, const int* in_sizes, int n_in,
                              void* d_out, int out_size)
{
    const float* x        = (const float*)d_in[0];
    const float* position = (const float*)d_in[1];
    const float* ln_in_w  = (const float*)d_in[2];
    const float* ln_in_b  = (const float*)d_in[3];
    const float* pos_w1   = (const float*)d_in[4];
    const float* pos_b1   = (const float*)d_in[5];
    const float* pos_w2   = (const float*)d_in[6];
    const float* pos_b2   = (const float*)d_in[7];
    const float* in_w     = (const float*)d_in[8];
    const float* cx_w     = (const float*)d_in[9];
    const float* cz_w     = (const float*)d_in[10];
    const float* xp_w     = (const float*)d_in[11];
    const float* dt_w     = (const float*)d_in[12];
    const float* dt_b     = (const float*)d_in[13];
    const float* Alog     = (const float*)d_in[14];
    const float* Dp       = (const float*)d_in[15];
    const float* out_w    = (const float*)d_in[16];
    const float* mix_w    = (const float*)d_in[17];
    const float* ln_out_w = (const float*)d_in[18];
    const float* ln_out_b = (const float*)d_in[19];
    float* out = (float*)d_out;

    float  *p_h, *p_pos, *p_ubig, *p_xzc, *p_mixed, *p_owT, *p_wbig,
           *p_inwr, *p_pw2r, *p_mixwr;
    float2 *p_dx, *p_bc;
    cudaGetSymbolAddress((void**)&p_h,     g_h);
    cudaGetSymbolAddress((void**)&p_pos,   g_pos);
    cudaGetSymbolAddress((void**)&p_ubig,  g_ubig);
    cudaGetSymbolAddress((void**)&p_xzc,   g_xzc);
    cudaGetSymbolAddress((void**)&p_dx,    g_dx);
    cudaGetSymbolAddress((void**)&p_bc,    g_bc);
    cudaGetSymbolAddress((void**)&p_mixed, g_mixed);
    cudaGetSymbolAddress((void**)&p_owT,   g_owT);
    cudaGetSymbolAddress((void**)&p_wbig,  g_wbig);
    cudaGetSymbolAddress((void**)&p_inwr,  g_inwr);
    cudaGetSymbolAddress((void**)&p_pw2r,  g_pw2r);
    cudaGetSymbolAddress((void**)&p_mixwr, g_mixwr);

    const int prep_smem = (12288 + 8448 + RPER * 256 + RPER * 48) * 4; // 102400
    cudaFuncSetAttribute(k_prep, cudaFuncAttributeMaxDynamicSharedMemorySize,
                         prep_smem);
    const int gemm_smem = 4 * 4096 * 4;   // 64 KB
    cudaFuncSetAttribute(gemm_tf32, cudaFuncAttributeMaxDynamicSharedMemorySize,
                         gemm_smem);

    // secondary stream + fork/join events (fresh per call; host-side objects
    // only — no device memory; capture-legal)
    cudaStream_t sB;
    cudaStreamCreateWithFlags(&sB, cudaStreamNonBlocking);
    cudaEvent_t ev0, evInw, evFold;
    cudaEventCreateWithFlags(&ev0,    cudaEventDisableTiming);
    cudaEventCreateWithFlags(&evInw,  cudaEventDisableTiming);
    cudaEventCreateWithFlags(&evFold, cudaEventDisableTiming);

    // ---- main chain start ------------------------------------------------
    // L1: pos_w2 round (needed by pos GEMM)
    k_round<<<256, 256>>>(pos_w2, p_pw2r, DD * 128);
    // L2-L3: position MLP
    k_pos_h<<<ROWS, 128>>>(position, pos_w1, pos_b1, p_h);
    gemm_tf32<<<dim3(4, 128), 256, gemm_smem>>>(p_h, 128, p_pw2r, 128,
                                                p_pos, DD, 128);
    // L4: LN(x) + pos -> ubig si columns
    k_ln_in<<<ROWS, 256>>>(x, p_pos, ln_in_w, ln_in_b, pos_b2, p_ubig);

    // ---- fork side stream -------------------------------------------------
    cudaEventRecord(ev0, 0);
    cudaStreamWaitEvent(sB, ev0, 0);
    // L5 (sB): in_w round — must precede in-proj
    k_round<<<2048, 256, 0, sB>>>(in_w, p_inwr, 2 * DD * DD);
    cudaEventRecord(evInw, sB);

    // ---- main chain continues --------------------------------------------
    cudaStreamWaitEvent(0, evInw, 0);
    // L6: fused in-proj GEMM (both dirs, N=1024)  <- ncu capture target
    gemm_tf32<<<dim3(8, 128), 256, gemm_smem>>>(p_ubig + 1024, UCOLS,
                                                p_inwr, DD, p_xzc, 1024, DD);
    // L7: 3-phase prep
    k_prep<<<dim3(ROWS / RPER, 2), 256, prep_smem>>>(
        p_xzc, cx_w, cz_w, xp_w, dt_w, dt_b, p_dx, p_bc, p_ubig);
    // L8: both scans
    k_scan<<<128, 256>>>(p_dx, p_bc, Alog, Dp, p_ubig);

    // ---- side stream: weight-fold chain (overlaps in-proj/prep/scan) ------
    k_transpose<<<dim3(16, 16, 2), dim3(32, 32), 0, sB>>>(out_w, p_owT);
    k_round<<<3072, 256, 0, sB>>>(mix_w, p_mixwr, DD * UCOLS);
    gemm_tf32<<<dim3(4, 4), 256, gemm_smem, sB>>>(p_mixwr,       UCOLS, p_owT,
                                                  DD, p_wbig,       UCOLS, DD);
    gemm_tf32<<<dim3(4, 4), 256, gemm_smem, sB>>>(p_mixwr + 512, UCOLS,
                                                  p_owT + DD * DD,
                                                  DD, p_wbig + 512, UCOLS, DD);
    k_copytail<<<1024, 256, 0, sB>>>(mix_w, p_wbig);
    cudaEventRecord(evFold, sB);

    // ---- join + tail ------------------------------------------------------
    cudaStreamWaitEvent(0, evFold, 0);
    // fused out-proj + mix GEMM (tf32, K=1536)
    gemm_tf32<<<dim3(4, 128), 256, gemm_smem>>>(p_ubig, UCOLS, p_wbig, UCOLS,
                                                p_mixed, DD, UCOLS);
    // output LN
    k_ln_out<<<ROWS, 256>>>(p_mixed, ln_out_w, ln_out_b, out);
}

// round 17
// speedup vs baseline: 5.7982x; 1.0064x over previous
#include <cuda_runtime.h>
#include <cuda_bf16.h>
#include <cstdint>

// Problem constants
#define BB 8
#define LL 2048
#define DD 512
#define II 256
#define SS 8
#define DTR 32
#define ROWS (BB*LL)          // 16384
#define UCOLS 1536
#define RPER 16               // rows per k_prep block

// ---------------- scratch (static device globals; no runtime alloc) -------
__device__ float  g_h    [ROWS * 128];       // pos hidden (tf32-rounded)
__device__ float  g_pos  [ROWS * DD];        // pos MLP output, later si-partial
__device__ float  g_ubig [ROWS * UCOLS];     // [y_f, zb_f, y_b, zb_b, si] (tf32)
__device__ float  g_xzc  [ROWS * 1024];      // fused in-proj output (both dirs)
__device__ float2 g_dx   [2 * ROWS * II];    // (delta, xb) pairs
__device__ float2 g_bc   [2 * ROWS * SS];    // (bt, ct) pairs
__device__ float  g_mixed[ROWS * DD];
__device__ float  g_owT  [2 * DD * DD];      // transposed scan_out_w (tf32)
__device__ float  g_wbig [DD * UCOLS];       // folded mix weight (tf32)
__device__ float  g_inwr [2 * DD * DD];      // tf32-rounded in_w
__device__ float  g_pw2r [DD * 128];         // tf32-rounded pos_w2
__device__ float  g_mixwr[DD * UCOLS];       // tf32-rounded mix_w

// ---------------- tf32 helpers ---------------------------------------------
__device__ __forceinline__ float tf32r(float f) {
    uint32_t r;
    asm("cvt.rna.tf32.f32 %0, %1;" : "=r"(r) : "f"(f));
    return __uint_as_float(r);
}

#define MMA_TF32(d, a, b) \
    asm volatile("mma.sync.aligned.m16n8k8.row.col.f32.tf32.tf32.f32 " \
        "{%0,%1,%2,%3}, {%4,%5,%6,%7}, {%8,%9}, {%0,%1,%2,%3};" \
        : "+f"(d[0]), "+f"(d[1]), "+f"(d[2]), "+f"(d[3]) \
        : "r"(a[0]), "r"(a[1]), "r"(a[2]), "r"(a[3]), "r"(b[0]), "r"(b[1]))

__device__ __forceinline__ void cp16(uint32_t dst, const float* src) {
    asm volatile("cp.async.cg.shared.global [%0], [%1], 16;"
                 :: "r"(dst), "l"(src));
}

// swizzled element offset within a 128x16 stage tile (element units)
__device__ __forceinline__ int dstoff(int r, int g) {
    return r * 16 + ((g ^ ((r >> 1) & 3)) << 2);
}

// ---------------- tf32 GEMM (cp.async, pre-rounded inputs) -----------------
// C[m,n] = sum_k A[m,k]*W[n,k].  BM=BN=128, BK=16, 4-stage pipeline.
// Inputs MUST be tf32-rounded already (raw-byte staging, no cvt).
__global__ __launch_bounds__(256, 2) void gemm_tf32(
    const float* __restrict__ A, int lda,
    const float* __restrict__ W, int ldw,
    float* __restrict__ C, int ldc, int K)
{
    extern __shared__ uint32_t sm[];   // 4 stages x (2048 A + 2048 W) u32
    const int bm = blockIdx.y * 128;
    const int bn = blockIdx.x * 128;
    const int tid = threadIdx.x;
    const int lane = tid & 31, wid = tid >> 5;
    const int wm = (wid & 1) * 64, wn = (wid >> 1) * 32;
    const int gr = lane >> 2, gc = lane & 3;
    const int sw = (gr >> 1) & 3;      // per-lane swizzle constant
    const int aG0 = (0 ^ sw) * 4, aG1 = (1 ^ sw) * 4;
    const int aG2 = (2 ^ sw) * 4, aG3 = (3 ^ sw) * 4;

    const int r0s = tid >> 2;          // staging row (u=0)
    const int gs  = tid & 3;           // staging 16B group
    uint32_t sb = (uint32_t)__cvta_generic_to_shared(sm);
    const int nk = K >> 4;

    float acc[4][4][4];
    #pragma unroll
    for (int mf = 0; mf < 4; mf++)
        #pragma unroll
        for (int nf = 0; nf < 4; nf++)
            #pragma unroll
            for (int e = 0; e < 4; e++) acc[mf][nf][e] = 0.f;

    // prologue: stages 0..2
    #pragma unroll
    for (int st = 0; st < 3; st++) {
        int k0 = st << 4;
        #pragma unroll
        for (int u = 0; u < 2; u++) {
            int r = r0s + u * 64;
            cp16(sb + (uint32_t)(st * 4096 + dstoff(r, gs)) * 4,
                 &A[(size_t)(bm + r) * lda + k0 + gs * 4]);
            cp16(sb + (uint32_t)(st * 4096 + 2048 + dstoff(r, gs)) * 4,
                 &W[(size_t)(bn + r) * ldw + k0 + gs * 4]);
        }
        asm volatile("cp.async.commit_group;");
    }

    for (int kt = 0; kt < nk; kt++) {
        asm volatile("cp.async.wait_group 2;");
        __syncthreads();
        if (kt + 3 < nk) {
            int st = kt + 3, slot = st & 3, k0 = st << 4;
            #pragma unroll
            for (int u = 0; u < 2; u++) {
                int r = r0s + u * 64;
                cp16(sb + (uint32_t)(slot * 4096 + dstoff(r, gs)) * 4,
                     &A[(size_t)(bm + r) * lda + k0 + gs * 4]);
                cp16(sb + (uint32_t)(slot * 4096 + 2048 + dstoff(r, gs)) * 4,
                     &W[(size_t)(bn + r) * ldw + k0 + gs * 4]);
            }
        }
        asm volatile("cp.async.commit_group;");

        const uint32_t* Asl = sm + (kt & 3) * 4096;
        const uint32_t* Wsl = Asl + 2048;
        #pragma unroll
        for (int ks = 0; ks < 2; ks++) {
            const int gA = ks ? aG2 : aG0;
            const int gB = ks ? aG3 : aG1;
            uint32_t af[4][4];
            #pragma unroll
            for (int mf = 0; mf < 4; mf++) {
                int rb = (wm + mf * 16 + gr) * 16 + gc;
                af[mf][0] = Asl[rb + gA];
                af[mf][1] = Asl[rb + 128 + gA];   // +8 rows
                af[mf][2] = Asl[rb + gB];
                af[mf][3] = Asl[rb + 128 + gB];
            }
            uint32_t bf[4][2];
            #pragma unroll
            for (int nf = 0; nf < 4; nf++) {
                int rb = (wn + nf * 8 + gr) * 16 + gc;
                bf[nf][0] = Wsl[rb + gA];
                bf[nf][1] = Wsl[rb + gB];
            }
            #pragma unroll
            for (int mf = 0; mf < 4; mf++)
                #pragma unroll
                for (int nf = 0; nf < 4; nf++)
                    MMA_TF32(acc[mf][nf], af[mf], bf[nf]);
        }
    }

    #pragma unroll
    for (int mf = 0; mf < 4; mf++) {
        #pragma unroll
        for (int nf = 0; nf < 4; nf++) {
            int r0 = bm + wm + mf * 16 + gr;
            int cc = bn + wn + nf * 8 + gc * 2;
            float2 v01 = make_float2(acc[mf][nf][0], acc[mf][nf][1]);
            float2 v23 = make_float2(acc[mf][nf][2], acc[mf][nf][3]);
            *reinterpret_cast<float2*>(&C[(size_t)r0 * ldc + cc]) = v01;
            *reinterpret_cast<float2*>(&C[(size_t)(r0 + 8) * ldc + cc]) = v23;
        }
    }
}

// ---------------- transpose 512x512 (per dir), tf32-rounds output ----------
__global__ void k_transpose(const float* __restrict__ src, float* __restrict__ dst)
{
    __shared__ float tile[32][33];
    int d = blockIdx.z;
    src += (size_t)d * DD * DD;
    dst += (size_t)d * DD * DD;
    int x = blockIdx.x * 32 + threadIdx.x;
    int y = blockIdx.y * 32 + threadIdx.y;
    tile[threadIdx.y][threadIdx.x] = src[(size_t)y * DD + x];
    __syncthreads();
    x = blockIdx.y * 32 + threadIdx.x;
    y = blockIdx.x * 32 + threadIdx.y;
    dst[(size_t)y * DD + x] = tf32r(tile[threadIdx.x][threadIdx.y]);
}

// copy mix_w[:,1024:1536] into g_wbig[:,1024:1536], tf32-rounded
__global__ void k_copytail(const float* __restrict__ mixw, float* __restrict__ wbig)
{
    int idx = blockIdx.x * 256 + threadIdx.x;
    int n = idx >> 9, j = idx & 511;
    wbig[(size_t)n * UCOLS + 1024 + j] = tf32r(mixw[(size_t)n * UCOLS + 1024 + j]);
}

// tf32 round-copy
__global__ void k_round(const float* __restrict__ s, float* __restrict__ d, int n)
{
    int i = blockIdx.x * 256 + threadIdx.x;
    if (i < n) d[i] = tf32r(s[i]);
}

// ---------------- position MLP layer 1 (6 -> 128, exact GELU) --------------
__global__ void k_pos_h(const float* __restrict__ position,
                        const float* __restrict__ pw1,
                        const float* __restrict__ pb1,
                        float* __restrict__ h)
{
    int r = blockIdx.x, j = threadIdx.x;
    __shared__ float p[6];
    if (j < 6) p[j] = position[(size_t)r * 6 + j];
    __syncthreads();
    float acc = pb1[j];
    #pragma unroll
    for (int c = 0; c < 6; c++) acc = fmaf(pw1[j * 6 + c], p[c], acc);
    float g = 0.5f * acc * (1.f + erff(acc * 0.70710678118654752f));
    h[(size_t)r * 128 + j] = tf32r(g);
}

// ---------------- block reduce helper (256 threads) ------------------------
__device__ __forceinline__ float block_sum256(float v, float* sw, int t)
{
    #pragma unroll
    for (int o = 16; o > 0; o >>= 1) v += __shfl_xor_sync(0xffffffffu, v, o);
    if ((t & 31) == 0) sw[t >> 5] = v;
    __syncthreads();
    float r = sw[t & 7];
    #pragma unroll
    for (int o = 4; o > 0; o >>= 1) r += __shfl_xor_sync(0xffffffffu, r, o);
    return r;
}

// ---------------- input LN + pos add -> ubig si columns (tf32) -------------
__global__ void k_ln_in(const float* __restrict__ x,
                        const float* __restrict__ pos2,
                        const float* __restrict__ lnw, const float* __restrict__ lnb,
                        const float* __restrict__ pb2,
                        float* __restrict__ ubig)
{
    int r = blockIdx.x, t = threadIdx.x;
    const float* xr = x + (size_t)r * DD;
    float v0 = xr[t], v1 = xr[t + 256];
    __shared__ float sw[8];
    float total = block_sum256(v0 + v1, sw, t);
    float m = total * (1.f / 512.f);
    __syncthreads();
    float d0 = v0 - m, d1 = v1 - m;
    float vsum = block_sum256(d0 * d0 + d1 * d1, sw, t);
    float rs = rsqrtf(vsum * (1.f / 512.f) + 1e-6f);
    const float* pr = pos2 + (size_t)r * DD;
    float* u = ubig + (size_t)r * UCOLS + 1024;
    u[t]       = tf32r(d0 * rs * lnw[t]       + lnb[t]       + pr[t]       + pb2[t]);
    u[t + 256] = tf32r(d1 * rs * lnw[t + 256] + lnb[t + 256] + pr[t + 256] + pb2[t + 256]);
}

// ---------------- conv+silu + proj + delta ("prep"), 3-phase ---------------
// grid (ROWS/RPER, 2). Weights staged once; 3 barriers per block total.
__global__ __launch_bounds__(256) void k_prep(
    const float* __restrict__ xzc,
    const float* __restrict__ cxw, const float* __restrict__ czw,
    const float* __restrict__ xpw,
    const float* __restrict__ dtw, const float* __restrict__ dtb,
    float2* __restrict__ dx, float2* __restrict__ bc,
    float* __restrict__ ubig)
{
    const int t = threadIdx.x;
    const int d = blockIdx.y;
    const int r0 = blockIdx.x * RPER;

    extern __shared__ float smf[];
    float* sxpw  = smf;                    // 48*256   = 12288
    float* sdt   = smf + 12288;            // 256*33   = 8448
    float* sxb   = smf + 12288 + 8448;     // RPER*256 = 4096
    float* sproj = sxb + RPER * 256;       // RPER*48  = 768
                                           // total 25600 floats = 102400 B
    // stage xp_w[d] (48x256) coalesced
    {
        const float4* xg = reinterpret_cast<const float4*>(xpw + (size_t)d * 48 * II);
        #pragma unroll
        for (int u = 0; u < 12; u++)
            reinterpret_cast<float4*>(sxpw)[t + u * 256] = xg[t + u * 256];
    }
    // stage dt_w[d] (256x32) into padded rows
    {
        const float4* dtg = reinterpret_cast<const float4*>(dtw + (size_t)d * II * DTR);
        #pragma unroll
        for (int u = 0; u < 8; u++) {
            int f = t + u * 256;
            float4 v = dtg[f];
            int tr = f >> 3, kc = (f & 7) * 4;
            sdt[tr * 33 + kc + 0] = v.x;
            sdt[tr * 33 + kc + 1] = v.y;
            sdt[tr * 33 + kc + 2] = v.z;
            sdt[tr * 33 + kc + 3] = v.w;
        }
    }

    const float* cwp = cxw + (size_t)(d * II + t) * 3;
    const float* zwp = czw + (size_t)(d * II + t) * 3;
    float cw0 = cwp[0], cw1 = cwp[1], cw2 = cwp[2];
    float zw0 = zwp[0], zw1 = zwp[1], zw2 = zwp[2];
    float bias = dtb[d * II + t];
    const int warp = t >> 5, lane = t & 31;

    // phase 1: conv + SiLU for all RPER rows (no barriers inside)
    float xv[RPER];
    #pragma unroll 4
    for (int rr = 0; rr < RPER; rr++) {
        int r = r0 + rr;
        int l = r & (LL - 1);
        size_t row = (size_t)r * 1024 + d * 512;
        float x0 = xzc[row + t];
        float z0 = xzc[row + 256 + t];
        float xm = 0.f, xp = 0.f, zm = 0.f, zp = 0.f;
        if (l > 0)      { xm = xzc[row - 1024 + t]; zm = xzc[row - 1024 + 256 + t]; }
        if (l < LL - 1) { xp = xzc[row + 1024 + t]; zp = xzc[row + 1024 + 256 + t]; }
        float xc, zc;
        if (d == 0) {
            xc = cw0 * xm + cw1 * x0 + cw2 * xp;
            zc = zw0 * zm + zw1 * z0 + zw2 * zp;
        } else {
            xc = cw0 * xp + cw1 * x0 + cw2 * xm;
            zc = zw0 * zp + zw1 * z0 + zw2 * zm;
        }
        float xbv = xc / (1.f + __expf(-xc));
        float zbv = zc / (1.f + __expf(-zc));
        xv[rr] = xbv;
        sxb[rr * 256 + t] = xbv;
        ubig[(size_t)(r0 + rr) * UCOLS + (d ? 768 : 256) + t] = tf32r(zbv);
    }
    __syncthreads();   // staging + phase1 visible

    // phase 2: projections for all rows (each warp owns 6 j-outputs)
    #pragma unroll
    for (int jj = 0; jj < 6; jj++) {
        int j = warp * 6 + jj;
        const float* wr = sxpw + j * 256;
        float w0 = wr[lane],       w1 = wr[lane + 32],  w2 = wr[lane + 64],
              w3 = wr[lane + 96],  w4 = wr[lane + 128], w5 = wr[lane + 160],
              w6 = wr[lane + 192], w7 = wr[lane + 224];
        for (int rr = 0; rr < RPER; rr++) {
            const float* xb = sxb + rr * 256;
            float p = w0 * xb[lane];
            p = fmaf(w1, xb[lane + 32], p);
            p = fmaf(w2, xb[lane + 64], p);
            p = fmaf(w3, xb[lane + 96], p);
            p = fmaf(w4, xb[lane + 128], p);
            p = fmaf(w5, xb[lane + 160], p);
            p = fmaf(w6, xb[lane + 192], p);
            p = fmaf(w7, xb[lane + 224], p);
            #pragma unroll
            for (int o = 16; o > 0; o >>= 1) p += __shfl_xor_sync(0xffffffffu, p, o);
            if (lane == 0) sproj[rr * 48 + j] = p;
        }
    }
    __syncthreads();

    // phase 3: bt/ct (128 threads cover 16 rows x 8 s), then delta for all rows
    if (t < RPER * 8) {
        int rr = t >> 3, s = t & 7;
        bc[(size_t)(d * ROWS + r0 + rr) * SS + s] =
            make_float2(tanhf(sproj[rr * 48 + 32 + s]), tanhf(sproj[rr * 48 + 40 + s]));
    }
    const float* sr = &sdt[t * 33];
    #pragma unroll 2
    for (int rr = 0; rr < RPER; rr++) {
        const float* pj = sproj + rr * 48;
        float acc = bias;
        #pragma unroll
        for (int k = 0; k < DTR; k++) acc = fmaf(pj[k], sr[k], acc);
        float sp = (acc > 20.f) ? acc : log1pf(expf(acc));
        sp = fminf(fmaxf(sp, 1e-4f), 1.0f);
        dx[(size_t)(d * ROWS + r0 + rr) * II + t] = make_float2(sp, xv[rr]);
    }
}

// ---------------- sequential selective scan (batched prefetch) -------------
__global__ __launch_bounds__(256) void k_scan(
    const float2* __restrict__ dx, const float2* __restrict__ bc,
    const float* __restrict__ Alog, const float* __restrict__ Dp,
    float* __restrict__ ubig)
{
    int tid = blockIdx.x * 256 + threadIdx.x;
    int s = tid & 7;
    int chain = tid >> 3;
    int i = chain & (II - 1);
    int b = (chain >> 8) & (BB - 1);
    int d = chain >> 11;

    float a = log1pf(expf(Alog[(d * II + i) * SS + s])) + 1e-4f;
    float dp = Dp[d * II + i];

    int l0  = d ? (LL - 1) : 0;
    int sDX = d ? -II : II;
    int sBC = d ? -SS : SS;
    int sU  = d ? -UCOLS : UCOLS;
    int oDX = (d * ROWS + b * LL + l0) * II + i;
    int oBC = (d * ROWS + b * LL + l0) * SS + s;
    int oU  = b * LL * UCOLS + (d ? 512 : 0) + i + l0 * UCOLS;

    float state = 0.f;
    float2 cd[8], cb[8];
    #pragma unroll
    for (int u = 0; u < 8; u++) {
        cd[u] = dx[oDX + u * sDX];
        cb[u] = bc[oBC + u * sBC];
    }
    for (int n0 = 0; n0 < LL; n0 += 8) {
        float2 nd[8], nb[8];
        bool more = (n0 + 8 < LL);
        if (more) {
            int p1 = oDX + 8 * sDX;
            int p2 = oBC + 8 * sBC;
            #pragma unroll
            for (int u = 0; u < 8; u++) {
                nd[u] = dx[p1 + u * sDX];
                nb[u] = bc[p2 + u * sBC];
            }
        }
        #pragma unroll
        for (int u = 0; u < 8; u++) {
            float dec = __expf(-cd[u].x * a);
            dec = fminf(fmaxf(dec, 1e-4f), 1.0f);
            state = fmaf(dec, state, (1.f - dec) * (cb[u].x * cd[u].y));
            float part = state * cb[u].y;
            part += __shfl_xor_sync(0xffffffffu, part, 1);
            part += __shfl_xor_sync(0xffffffffu, part, 2);
            part += __shfl_xor_sync(0xffffffffu, part, 4);
            if (s == 0) ubig[oU + u * sU] = tf32r(part + dp * cd[u].y);
        }
        if (more) {
            #pragma unroll
            for (int u = 0; u < 8; u++) { cd[u] = nd[u]; cb[u] = nb[u]; }
        }
        oDX += 8 * sDX; oBC += 8 * sBC; oU += 8 * sU;
    }
}

// ---------------- output LN (sums two partial GEMM outputs) ----------------
__global__ void k_ln_out(const float* __restrict__ mixed,
                         const float* __restrict__ mixed2,
                         const float* __restrict__ w, const float* __restrict__ bias,
                         float* __restrict__ out)
{
    int r = blockIdx.x, t = threadIdx.x;
    const float* xr = mixed + (size_t)r * DD;
    const float* yr = mixed2 + (size_t)r * DD;
    float v0 = xr[t] + yr[t];
    float v1 = xr[t + 256] + yr[t + 256];
    __shared__ float sw[8];
    float total = block_sum256(v0 + v1, sw, t);
    float m = total * (1.f / 512.f);
    __syncthreads();
    float d0 = v0 - m, d1 = v1 - m;
    float vsum = block_sum256(d0 * d0 + d1 * d1, sw, t);
    float rs = rsqrtf(vsum * (1.f / 512.f) + 1e-6f);
    float* orow = out + (size_t)r * DD;
    orow[t]       = d0 * rs * w[t]       + bias[t];
    orow[t + 256] = d1 * rs * w[t + 256] + bias[t + 256];
}

// ---------------- host launch ----------------------------------------------
extern "C" void kernel_launch(void* const* d_in, const int* in_sizes, int n_in,
                              void* d_out, int out_size)
{
    const float* x        = (const float*)d_in[0];
    const float* position = (const float*)d_in[1];
    const float* ln_in_w  = (const float*)d_in[2];
    const float* ln_in_b  = (const float*)d_in[3];
    const float* pos_w1   = (const float*)d_in[4];
    const float* pos_b1   = (const float*)d_in[5];
    const float* pos_w2   = (const float*)d_in[6];
    const float* pos_b2   = (const float*)d_in[7];
    const float* in_w     = (const float*)d_in[8];
    const float* cx_w     = (const float*)d_in[9];
    const float* cz_w     = (const float*)d_in[10];
    const float* xp_w     = (const float*)d_in[11];
    const float* dt_w     = (const float*)d_in[12];
    const float* dt_b     = (const float*)d_in[13];
    const float* Alog     = (const float*)d_in[14];
    const float* Dp       = (const float*)d_in[15];
    const float* out_w    = (const float*)d_in[16];
    const float* mix_w    = (const float*)d_in[17];
    const float* ln_out_w = (const float*)d_in[18];
    const float* ln_out_b = (const float*)d_in[19];
    float* out = (float*)d_out;

    float  *p_h, *p_pos, *p_ubig, *p_xzc, *p_mixed, *p_owT, *p_wbig,
           *p_inwr, *p_pw2r, *p_mixwr;
    float2 *p_dx, *p_bc;
    cudaGetSymbolAddress((void**)&p_h,     g_h);
    cudaGetSymbolAddress((void**)&p_pos,   g_pos);
    cudaGetSymbolAddress((void**)&p_ubig,  g_ubig);
    cudaGetSymbolAddress((void**)&p_xzc,   g_xzc);
    cudaGetSymbolAddress((void**)&p_dx,    g_dx);
    cudaGetSymbolAddress((void**)&p_bc,    g_bc);
    cudaGetSymbolAddress((void**)&p_mixed, g_mixed);
    cudaGetSymbolAddress((void**)&p_owT,   g_owT);
    cudaGetSymbolAddress((void**)&p_wbig,  g_wbig);
    cudaGetSymbolAddress((void**)&p_inwr,  g_inwr);
    cudaGetSymbolAddress((void**)&p_pw2r,  g_pw2r);
    cudaGetSymbolAddress((void**)&p_mixwr, g_mixwr);

    const int prep_smem = (12288 + 8448 + RPER * 256 + RPER * 48) * 4; // 102400
    cudaFuncSetAttribute(k_prep, cudaFuncAttributeMaxDynamicSharedMemorySize,
                         prep_smem);
    const int gemm_smem = 4 * 4096 * 4;   // 64 KB
    cudaFuncSetAttribute(gemm_tf32, cudaFuncAttributeMaxDynamicSharedMemorySize,
                         gemm_smem);

    // secondary stream + fork/join events (fresh per call; host-side objects
    // only — no device memory; capture-legal)
    cudaStream_t sB;
    cudaStreamCreateWithFlags(&sB, cudaStreamNonBlocking);
    cudaEvent_t ev0, evInw, evSide;
    cudaEventCreateWithFlags(&ev0,    cudaEventDisableTiming);
    cudaEventCreateWithFlags(&evInw,  cudaEventDisableTiming);
    cudaEventCreateWithFlags(&evSide, cudaEventDisableTiming);

    // ---- main chain start ------------------------------------------------
    k_round<<<256, 256>>>(pos_w2, p_pw2r, DD * 128);
    k_pos_h<<<ROWS, 128>>>(position, pos_w1, pos_b1, p_h);
    gemm_tf32<<<dim3(4, 128), 256, gemm_smem>>>(p_h, 128, p_pw2r, 128,
                                                p_pos, DD, 128);
    // LN(x) + pos -> ubig si columns (also: pos buffer dead after this)
    k_ln_in<<<ROWS, 256>>>(x, p_pos, ln_in_w, ln_in_b, pos_b2, p_ubig);

    // ---- fork side stream (after ln_in) -----------------------------------
    cudaEventRecord(ev0, 0);
    cudaStreamWaitEvent(sB, ev0, 0);
    // in_w round — main chain waits on this before in-proj
    k_round<<<2048, 256, 0, sB>>>(in_w, p_inwr, 2 * DD * DD);
    cudaEventRecord(evInw, sB);
    // si-part of the mix: wbig tail cols, then partial GEMM (K=512) into
    // mixed2 (reuses g_pos, which is dead after ln_in)
    k_copytail<<<1024, 256, 0, sB>>>(mix_w, p_wbig);
    gemm_tf32<<<dim3(4, 128), 256, gemm_smem, sB>>>(
        p_ubig + 1024, UCOLS, p_wbig + 1024, UCOLS, p_pos, DD, DD);
    // weight-fold chain (independent of main until final mix GEMM)
    k_transpose<<<dim3(16, 16, 2), dim3(32, 32), 0, sB>>>(out_w, p_owT);
    k_round<<<3072, 256, 0, sB>>>(mix_w, p_mixwr, DD * UCOLS);
    gemm_tf32<<<dim3(4, 4), 256, gemm_smem, sB>>>(p_mixwr,       UCOLS, p_owT,
                                                  DD, p_wbig,       UCOLS, DD);
    gemm_tf32<<<dim3(4, 4), 256, gemm_smem, sB>>>(p_mixwr + 512, UCOLS,
                                                  p_owT + DD * DD,
                                                  DD, p_wbig + 512, UCOLS, DD);
    cudaEventRecord(evSide, sB);

    // ---- main chain continues --------------------------------------------
    cudaStreamWaitEvent(0, evInw, 0);
    // fused in-proj GEMM (both dirs, N=1024)
    gemm_tf32<<<dim3(8, 128), 256, gemm_smem>>>(p_ubig + 1024, UCOLS,
                                                p_inwr, DD, p_xzc, 1024, DD);
    // 3-phase prep
    k_prep<<<dim3(ROWS / RPER, 2), 256, prep_smem>>>(
        p_xzc, cx_w, cz_w, xp_w, dt_w, dt_b, p_dx, p_bc, p_ubig);
    // both scans
    k_scan<<<128, 256>>>(p_dx, p_bc, Alog, Dp, p_ubig);

    // ---- join + tail ------------------------------------------------------
    cudaStreamWaitEvent(0, evSide, 0);
    // mix GEMM over y/zb columns only (K=1024); si part already in mixed2
    gemm_tf32<<<dim3(4, 128), 256, gemm_smem>>>(p_ubig, UCOLS, p_wbig, UCOLS,
                                                p_mixed, DD, 1024);
    // output LN over the sum of both partials
    k_ln_out<<<ROWS, 256>>>(p_mixed, p_pos, ln_out_w, ln_out_b, out);
}